// round 13
// baseline (speedup 1.0000x reference)
#include <cuda_runtime.h>
#include <cuda_fp16.h>
#include <cstdint>
#include <math.h>

#define NROW 8192
#define NFEAT 512
#define NHID 256
#define NCLASS 128
#define KSPLIT 4
#define KSPLIT2 4
#define KSPLITY 4

// ---------------------------------------------------------------------------
// Static device scratch (allocation-free rule)
// ---------------------------------------------------------------------------
__device__ __align__(16) float  g_adj[(size_t)NROW * NROW];     // fp32 logits
__device__ __align__(16) __half g_adjh[(size_t)NROW * NROW];    // fp16 softmax weights
__device__ __align__(16) __half g_fsh[(size_t)NROW * NFEAT];
__device__ __align__(16) __half g_fsl[(size_t)NROW * NFEAT];
__device__ __align__(16) __half g_fth[(size_t)NROW * NFEAT];
__device__ __align__(16) __half g_ftl[(size_t)NROW * NFEAT];
__device__ __align__(16) __half g_w1h[(size_t)NHID * NFEAT];
__device__ __align__(16) __half g_w1l[(size_t)NHID * NFEAT];
__device__ __align__(16) __half g_w2h[(size_t)NCLASS * NHID];
__device__ __align__(16) __half g_w2l[(size_t)NCLASS * NHID];
__device__ __align__(16) __half g_Y1T[(size_t)NHID * NROW];
__device__ __align__(16) __half g_Y2T[(size_t)NCLASS * NROW];
__device__ __align__(16) __half g_x1h[(size_t)NROW * NHID];
__device__ __align__(16) __half g_x1l[(size_t)NROW * NHID];
__device__ __align__(16) float  g_p1[(size_t)KSPLIT * NROW * NHID];
__device__ __align__(16) float  g_p2[(size_t)KSPLIT2 * NROW * NCLASS];
__device__ __align__(16) float  g_pY[(size_t)KSPLITY * NHID * NROW];  // Y partials

// ---------------------------------------------------------------------------
// PTX helpers (sm_80-era features; safe for the non-'a' PTX target)
// ---------------------------------------------------------------------------
__device__ __forceinline__ uint32_t smem_u32(const void* p) {
    uint32_t a;
    asm("{ .reg .u64 t; cvta.to.shared.u64 t, %1; cvt.u32.u64 %0, t; }" : "=r"(a) : "l"(p));
    return a;
}

#define CP_ASYNC16(dst, src) \
    asm volatile("cp.async.cg.shared.global [%0], [%1], 16;" :: "r"(dst), "l"(src))
#define CP_COMMIT() asm volatile("cp.async.commit_group;" ::: "memory")

template <int N>
__device__ __forceinline__ void cp_wait() {
    asm volatile("cp.async.wait_group %0;" :: "n"(N) : "memory");
}

__device__ __forceinline__ void ldsm4(uint32_t* r, uint32_t addr) {
    asm volatile("ldmatrix.sync.aligned.m8n8.x4.shared.b16 {%0,%1,%2,%3}, [%4];"
                 : "=r"(r[0]), "=r"(r[1]), "=r"(r[2]), "=r"(r[3]) : "r"(addr));
}

__device__ __forceinline__ void mma_f16(float* c, const uint32_t* a, uint32_t b0, uint32_t b1) {
    asm volatile(
        "mma.sync.aligned.m16n8k16.row.col.f32.f16.f16.f32 "
        "{%0,%1,%2,%3}, {%4,%5,%6,%7}, {%8,%9}, {%0,%1,%2,%3};"
        : "+f"(c[0]), "+f"(c[1]), "+f"(c[2]), "+f"(c[3])
        : "r"(a[0]), "r"(a[1]), "r"(a[2]), "r"(a[3]), "r"(b0), "r"(b1));
}

// ---------------------------------------------------------------------------
// Big 3-term GEMM (logits): C = A@B^T, 256x128x32 CTA tile, 512 threads
// (16 warps 4x4, warp tile 64x32), 3-stage cp.async, term-major MMA order.
// ---------------------------------------------------------------------------
__global__ void __launch_bounds__(512, 1)
hgemm3_256_kernel(const __half* __restrict__ Ah, const __half* __restrict__ Al,
                  const __half* __restrict__ Bh, const __half* __restrict__ Bl,
                  float* __restrict__ C, int M, int N, int K) {
    constexpr int PITCH = 80;
    constexpr int ATILE = 256 * PITCH;
    constexpr int BTILE = 128 * PITCH;
    constexpr int STG = 2 * ATILE + 2 * BTILE;
    constexpr int STAGES = 3;

    extern __shared__ char smem[];
    const uint32_t smb = smem_u32(smem);

    const int tid = threadIdx.x;
    const int wid = tid >> 5;
    const int lane = tid & 31;
    const int warp_m = wid >> 2;
    const int warp_n = wid & 3;
    const int bm = blockIdx.y * 256;
    const int bn = blockIdx.x * 128;

    const int ra = (lane & 7) + ((lane >> 3) & 1) * 8;
    const int ca = lane >> 4;
    const int rbx = (lane & 7) + ((lane >> 4) & 1) * 8;
    const int cbx = (lane >> 3) & 1;

    const int alr = tid >> 1, ahalf = tid & 1;
    const int blr = tid >> 2, bq = tid & 3;

    float acc[4][4][4];
#pragma unroll
    for (int i = 0; i < 4; i++)
#pragma unroll
        for (int j = 0; j < 4; j++)
#pragma unroll
            for (int q = 0; q < 4; q++) acc[i][j][q] = 0.0f;

    auto load_stage = [&](int buf, int kb) {
        uint32_t base = smb + buf * STG;
        const __half* pa = Ah + (size_t)(bm + alr) * K + kb;
        const __half* qa = Al + (size_t)(bm + alr) * K + kb;
        uint32_t rowa = base + alr * PITCH;
#pragma unroll
        for (int j = 0; j < 2; j++) {
            int ch = ahalf * 2 + j;
            CP_ASYNC16(rowa + ch * 16, pa + ch * 8);
            CP_ASYNC16(rowa + ATILE + ch * 16, qa + ch * 8);
        }
        const __half* pb = Bh + (size_t)(bn + blr) * K + kb;
        const __half* qb = Bl + (size_t)(bn + blr) * K + kb;
        uint32_t rowb = base + 2 * ATILE + blr * PITCH;
        CP_ASYNC16(rowb + bq * 16, pb + bq * 8);
        CP_ASYNC16(rowb + BTILE + bq * 16, qb + bq * 8);
    };

    const int niter = K / 32;

#pragma unroll
    for (int s = 0; s < STAGES - 1; s++) {
        if (s < niter) load_stage(s, s * 32);
        CP_COMMIT();
    }

    for (int it = 0; it < niter; it++) {
        cp_wait<STAGES - 2>();
        __syncthreads();

        const int buf = it % STAGES;
        const uint32_t aH = smb + buf * STG;
        const uint32_t aL = aH + ATILE;
        const uint32_t bH = aH + 2 * ATILE;
        const uint32_t bL = bH + BTILE;

#pragma unroll
        for (int ks = 0; ks < 2; ks++) {
            const uint32_t aco = (uint32_t)(2 * ks + ca) * 16;
            const uint32_t bco = (uint32_t)(2 * ks + cbx) * 16;

            uint32_t ah[4][4], al_[4][4];
#pragma unroll
            for (int mf = 0; mf < 4; mf++) {
                uint32_t ro = (uint32_t)(warp_m * 64 + mf * 16 + ra) * PITCH;
                ldsm4(ah[mf], aH + ro + aco);
                ldsm4(al_[mf], aL + ro + aco);
            }
#pragma unroll
            for (int nb = 0; nb < 2; nb++) {
                uint32_t ro = (uint32_t)(warp_n * 32 + nb * 16 + rbx) * PITCH;
                uint32_t bh[4], bl[4];
                ldsm4(bh, bH + ro + bco);
                ldsm4(bl, bL + ro + bco);
#pragma unroll
                for (int p = 0; p < 2; p++) {
                    const int nf = nb * 2 + p;
#pragma unroll
                    for (int mf = 0; mf < 4; mf++)
                        mma_f16(acc[mf][nf], ah[mf], bh[2 * p], bh[2 * p + 1]);
#pragma unroll
                    for (int mf = 0; mf < 4; mf++)
                        mma_f16(acc[mf][nf], ah[mf], bl[2 * p], bl[2 * p + 1]);
#pragma unroll
                    for (int mf = 0; mf < 4; mf++)
                        mma_f16(acc[mf][nf], al_[mf], bh[2 * p], bh[2 * p + 1]);
                }
            }
        }

        const int nidx = it + STAGES - 1;
        if (nidx < niter) load_stage(nidx % STAGES, nidx * 32);
        CP_COMMIT();
    }

    const int tr = lane >> 2;
    const int tc = lane & 3;
#pragma unroll
    for (int mf = 0; mf < 4; mf++) {
#pragma unroll
        for (int nf = 0; nf < 4; nf++) {
            int r0 = bm + warp_m * 64 + mf * 16 + tr;
            int col = bn + warp_n * 32 + nf * 8 + 2 * tc;
            *(float2*)(C + (size_t)r0 * N + col) = make_float2(acc[mf][nf][0], acc[mf][nf][1]);
            *(float2*)(C + (size_t)(r0 + 8) * N + col) =
                make_float2(acc[mf][nf][2], acc[mf][nf][3]);
        }
    }
}

// ---------------------------------------------------------------------------
// 3-term split-K GEMM (Y1T/Y2T): Cpart[z] = Ah@Bh^T + Ah@Bl^T + Al@Bh^T
// over K chunk z. 128x128x32 tile, 256 threads, 2-stage smem (81920B)
// -> 2 CTAs/SM. grid (N/128, M/128, NSPLIT).
// ---------------------------------------------------------------------------
template <int NSPLIT>
__global__ void __launch_bounds__(256, 2)
hgemm3_splitk_kernel(const __half* __restrict__ Ah, const __half* __restrict__ Al,
                     const __half* __restrict__ Bh, const __half* __restrict__ Bl,
                     float* __restrict__ Cpart, int M, int N, int K) {
    constexpr int PITCH = 80;
    constexpr int TILE = 128 * PITCH;
    constexpr int STG = 4 * TILE;          // Ah, Al, Bh, Bl tiles: 40960
    constexpr int STAGES = 2;

    extern __shared__ char smem[];
    const uint32_t smb = smem_u32(smem);

    const int tid = threadIdx.x;
    const int wid = tid >> 5;
    const int lane = tid & 31;
    const int warp_m = wid >> 2;
    const int warp_n = wid & 3;
    const int bm = blockIdx.y * 128;
    const int bn = blockIdx.x * 128;
    const int kbase = blockIdx.z * (K / NSPLIT);
    float* C = Cpart + (size_t)blockIdx.z * M * N;

    const int ra = (lane & 7) + ((lane >> 3) & 1) * 8;
    const int ca = lane >> 4;
    const int rbx = (lane & 7) + ((lane >> 4) & 1) * 8;
    const int cbx = (lane >> 3) & 1;

    const int lr = tid >> 1;               // 128 rows, 2 thr/row, 2 chunks each
    const int lc0 = (tid & 1) * 2;

    float acc[4][4][4];
#pragma unroll
    for (int i = 0; i < 4; i++)
#pragma unroll
        for (int j = 0; j < 4; j++)
#pragma unroll
            for (int q = 0; q < 4; q++) acc[i][j][q] = 0.0f;

    auto load_stage = [&](int buf, int kb) {
        uint32_t base = smb + buf * STG;
        const __half* pa = Ah + (size_t)(bm + lr) * K + kb;
        const __half* qa = Al + (size_t)(bm + lr) * K + kb;
        const __half* pb = Bh + (size_t)(bn + lr) * K + kb;
        const __half* qb = Bl + (size_t)(bn + lr) * K + kb;
        uint32_t rowd = base + lr * PITCH;
#pragma unroll
        for (int j = 0; j < 2; j++) {
            int ch = lc0 + j;
            CP_ASYNC16(rowd + ch * 16, pa + ch * 8);
            CP_ASYNC16(rowd + TILE + ch * 16, qa + ch * 8);
            CP_ASYNC16(rowd + 2 * TILE + ch * 16, pb + ch * 8);
            CP_ASYNC16(rowd + 3 * TILE + ch * 16, qb + ch * 8);
        }
    };

    const int niter = (K / NSPLIT) / 32;

    load_stage(0, kbase);
    CP_COMMIT();

    for (int it = 0; it < niter; it++) {
        cp_wait<0>();
        __syncthreads();
        if (it + 1 < niter) {
            load_stage((it + 1) & 1, kbase + (it + 1) * 32);
            CP_COMMIT();
        }

        const uint32_t aH = smb + (it & 1) * STG;
        const uint32_t aL = aH + TILE;
        const uint32_t bH = aH + 2 * TILE;
        const uint32_t bL = aH + 3 * TILE;

#pragma unroll
        for (int ks = 0; ks < 2; ks++) {
            const uint32_t aco = (uint32_t)(2 * ks + ca) * 16;
            const uint32_t bco = (uint32_t)(2 * ks + cbx) * 16;

            uint32_t ah[4][4], al_[4][4];
#pragma unroll
            for (int mf = 0; mf < 4; mf++) {
                uint32_t ro = (uint32_t)(warp_m * 64 + mf * 16 + ra) * PITCH;
                ldsm4(ah[mf], aH + ro + aco);
                ldsm4(al_[mf], aL + ro + aco);
            }
#pragma unroll
            for (int nb = 0; nb < 2; nb++) {
                uint32_t ro = (uint32_t)(warp_n * 32 + nb * 16 + rbx) * PITCH;
                uint32_t bh[4], bl[4];
                ldsm4(bh, bH + ro + bco);
                ldsm4(bl, bL + ro + bco);
#pragma unroll
                for (int p = 0; p < 2; p++) {
                    const int nf = nb * 2 + p;
#pragma unroll
                    for (int mf = 0; mf < 4; mf++)
                        mma_f16(acc[mf][nf], ah[mf], bh[2 * p], bh[2 * p + 1]);
#pragma unroll
                    for (int mf = 0; mf < 4; mf++)
                        mma_f16(acc[mf][nf], ah[mf], bl[2 * p], bl[2 * p + 1]);
#pragma unroll
                    for (int mf = 0; mf < 4; mf++)
                        mma_f16(acc[mf][nf], al_[mf], bh[2 * p], bh[2 * p + 1]);
                }
            }
        }
    }

    const int tr = lane >> 2;
    const int tc = lane & 3;
#pragma unroll
    for (int mf = 0; mf < 4; mf++) {
#pragma unroll
        for (int nf = 0; nf < 4; nf++) {
            int r0 = bm + warp_m * 64 + mf * 16 + tr;
            int col = bn + warp_n * 32 + nf * 8 + 2 * tc;
            *(float2*)(C + (size_t)r0 * N + col) = make_float2(acc[mf][nf][0], acc[mf][nf][1]);
            *(float2*)(C + (size_t)(r0 + 8) * N + col) =
                make_float2(acc[mf][nf][2], acc[mf][nf][3]);
        }
    }
}

// ---------------------------------------------------------------------------
// Split-K 1-term GEMM, wide: CTA tile 128(M) x 256(N) x 64, 512 threads
// (16 warps 2x8, warp tile 64x32). grid (N/256, M/128, KSPLIT)
// ---------------------------------------------------------------------------
__global__ void __launch_bounds__(512, 1)
hgemm1_splitk_wide_kernel(const __half* __restrict__ Ah, const __half* __restrict__ Bh,
                          float* __restrict__ Cpart, int M, int N, int K) {
    constexpr int KT = 64;
    constexpr int PITCH = 144;
    constexpr int ATILE = 128 * PITCH;
    constexpr int BTILE = 256 * PITCH;
    constexpr int STG = ATILE + BTILE;
    constexpr int STAGES = 3;

    extern __shared__ char smem[];
    const uint32_t smb = smem_u32(smem);

    const int tid = threadIdx.x;
    const int wid = tid >> 5;
    const int lane = tid & 31;
    const int warp_m = wid >> 3;
    const int warp_n = wid & 7;
    const int bm = blockIdx.y * 128;
    const int bn = blockIdx.x * 256;
    const int kbase = blockIdx.z * (K / KSPLIT);
    float* C = Cpart + (size_t)blockIdx.z * M * N;

    const int ra = (lane & 7) + ((lane >> 3) & 1) * 8;
    const int ca = lane >> 4;
    const int rbx = (lane & 7) + ((lane >> 4) & 1) * 8;
    const int cbx = (lane >> 3) & 1;

    const int alr = tid >> 2, aq = tid & 3;
    const int blr = tid >> 1, bhh = tid & 1;

    float acc[4][4][4];
#pragma unroll
    for (int i = 0; i < 4; i++)
#pragma unroll
        for (int j = 0; j < 4; j++)
#pragma unroll
            for (int q = 0; q < 4; q++) acc[i][j][q] = 0.0f;

    auto load_stage = [&](int buf, int kb) {
        uint32_t base = smb + buf * STG;
        const __half* pa = Ah + (size_t)(bm + alr) * K + kb;
        uint32_t rowa = base + alr * PITCH;
#pragma unroll
        for (int j = 0; j < 2; j++) {
            int ch = aq * 2 + j;
            CP_ASYNC16(rowa + ch * 16, pa + ch * 8);
        }
        const __half* pb = Bh + (size_t)(bn + blr) * K + kb;
        uint32_t rowb = base + ATILE + blr * PITCH;
#pragma unroll
        for (int j = 0; j < 4; j++) {
            int ch = bhh * 4 + j;
            CP_ASYNC16(rowb + ch * 16, pb + ch * 8);
        }
    };

    const int niter = (K / KSPLIT) / KT;

#pragma unroll
    for (int s = 0; s < STAGES - 1; s++) {
        if (s < niter) load_stage(s, kbase + s * KT);
        CP_COMMIT();
    }

    for (int it = 0; it < niter; it++) {
        cp_wait<STAGES - 2>();
        __syncthreads();

        const int buf = it % STAGES;
        const uint32_t aH = smb + buf * STG;
        const uint32_t bH = aH + ATILE;

#pragma unroll
        for (int ks = 0; ks < KT / 16; ks++) {
            const uint32_t aco = (uint32_t)(2 * ks + ca) * 16;
            const uint32_t bco = (uint32_t)(2 * ks + cbx) * 16;

            uint32_t ah[4][4];
#pragma unroll
            for (int mf = 0; mf < 4; mf++) {
                uint32_t ro = (uint32_t)(warp_m * 64 + mf * 16 + ra) * PITCH;
                ldsm4(ah[mf], aH + ro + aco);
            }
#pragma unroll
            for (int nb = 0; nb < 2; nb++) {
                uint32_t ro = (uint32_t)(warp_n * 32 + nb * 16 + rbx) * PITCH;
                uint32_t bh[4];
                ldsm4(bh, bH + ro + bco);
#pragma unroll
                for (int p = 0; p < 2; p++) {
                    const int nf = nb * 2 + p;
#pragma unroll
                    for (int mf = 0; mf < 4; mf++)
                        mma_f16(acc[mf][nf], ah[mf], bh[2 * p], bh[2 * p + 1]);
                }
            }
        }

        const int nidx = it + STAGES - 1;
        if (nidx < niter) load_stage(nidx % STAGES, kbase + nidx * KT);
        CP_COMMIT();
    }

    const int tr = lane >> 2;
    const int tc = lane & 3;
#pragma unroll
    for (int mf = 0; mf < 4; mf++) {
#pragma unroll
        for (int nf = 0; nf < 4; nf++) {
            int r0 = bm + warp_m * 64 + mf * 16 + tr;
            int col = bn + warp_n * 32 + nf * 8 + 2 * tc;
            *(float2*)(C + (size_t)r0 * N + col) = make_float2(acc[mf][nf][0], acc[mf][nf][1]);
            *(float2*)(C + (size_t)(r0 + 8) * N + col) =
                make_float2(acc[mf][nf][2], acc[mf][nf][3]);
        }
    }
}

// ---------------------------------------------------------------------------
// Split-K 1-term GEMM (128x128 tile, 256 threads); grid.z = NSPLIT.
// ---------------------------------------------------------------------------
template <int NSPLIT>
__global__ void __launch_bounds__(256, 1)
hgemm1_splitk_kernel(const __half* __restrict__ Ah, const __half* __restrict__ Bh,
                     float* __restrict__ Cpart, int M, int N, int K) {
    constexpr int KT = 64;
    constexpr int PITCH = 144;
    constexpr int TILE = 128 * PITCH;
    constexpr int STG = 2 * TILE;
    constexpr int STAGES = 3;
    constexpr int HC = 4;

    extern __shared__ char smem[];
    const uint32_t smb = smem_u32(smem);

    const int tid = threadIdx.x;
    const int wid = tid >> 5;
    const int lane = tid & 31;
    const int warp_m = wid >> 2;
    const int warp_n = wid & 3;
    const int bm = blockIdx.y * 128;
    const int bn = blockIdx.x * 128;
    const int kbase = blockIdx.z * (K / NSPLIT);
    float* C = Cpart + (size_t)blockIdx.z * M * N;

    const int ra = (lane & 7) + ((lane >> 3) & 1) * 8;
    const int ca = lane >> 4;
    const int rbx = (lane & 7) + ((lane >> 4) & 1) * 8;
    const int cbx = (lane >> 3) & 1;

    const int lr = tid >> 1;
    const int lc0 = (tid & 1) * HC;

    float acc[4][4][4];
#pragma unroll
    for (int i = 0; i < 4; i++)
#pragma unroll
        for (int j = 0; j < 4; j++)
#pragma unroll
            for (int q = 0; q < 4; q++) acc[i][j][q] = 0.0f;

    auto load_stage = [&](int buf, int kb) {
        uint32_t rowd = smb + buf * STG + lr * PITCH;
        const __half* pa = Ah + (size_t)(bm + lr) * K + kb;
        const __half* pb = Bh + (size_t)(bn + lr) * K + kb;
#pragma unroll
        for (int j = 0; j < HC; j++) {
            int ch = lc0 + j;
            CP_ASYNC16(rowd + ch * 16, pa + ch * 8);
            CP_ASYNC16(rowd + TILE + ch * 16, pb + ch * 8);
        }
    };

    const int niter = (K / NSPLIT) / KT;

#pragma unroll
    for (int s = 0; s < STAGES - 1; s++) {
        if (s < niter) load_stage(s, kbase + s * KT);
        CP_COMMIT();
    }

    for (int it = 0; it < niter; it++) {
        cp_wait<STAGES - 2>();
        __syncthreads();

        const int buf = it % STAGES;
        const uint32_t aH = smb + buf * STG;
        const uint32_t bH = aH + TILE;

#pragma unroll
        for (int ks = 0; ks < 4; ks++) {
            const uint32_t aco = (uint32_t)(2 * ks + ca) * 16;
            const uint32_t bco = (uint32_t)(2 * ks + cbx) * 16;

            uint32_t ah[4][4];
#pragma unroll
            for (int mf = 0; mf < 4; mf++) {
                uint32_t ro = (uint32_t)(warp_m * 64 + mf * 16 + ra) * PITCH;
                ldsm4(ah[mf], aH + ro + aco);
            }
#pragma unroll
            for (int nb = 0; nb < 2; nb++) {
                uint32_t ro = (uint32_t)(warp_n * 32 + nb * 16 + rbx) * PITCH;
                uint32_t bh[4];
                ldsm4(bh, bH + ro + bco);
#pragma unroll
                for (int p = 0; p < 2; p++) {
                    const int nf = nb * 2 + p;
#pragma unroll
                    for (int mf = 0; mf < 4; mf++)
                        mma_f16(acc[mf][nf], ah[mf], bh[2 * p], bh[2 * p + 1]);
                }
            }
        }

        const int nidx = it + STAGES - 1;
        if (nidx < niter) load_stage(nidx % STAGES, kbase + nidx * KT);
        CP_COMMIT();
    }

    const int tr = lane >> 2;
    const int tc = lane & 3;
#pragma unroll
    for (int mf = 0; mf < 4; mf++) {
#pragma unroll
        for (int nf = 0; nf < 4; nf++) {
            int r0 = bm + warp_m * 64 + mf * 16 + tr;
            int col = bn + warp_n * 32 + nf * 8 + 2 * tc;
            *(float2*)(C + (size_t)r0 * N + col) = make_float2(acc[mf][nf][0], acc[mf][nf][1]);
            *(float2*)(C + (size_t)(r0 + 8) * N + col) =
                make_float2(acc[mf][nf][2], acc[mf][nf][3]);
        }
    }
}

// ---------------------------------------------------------------------------
// Split-K reductions
//   reduce_split_kernel: fp32 out (+ optional hi/lo split)
//   reduce_h_kernel: fp16 out only
// ---------------------------------------------------------------------------
template <int NSPLIT, int DO_SPLIT>
__global__ void reduce_split_kernel(const float* __restrict__ part, float* __restrict__ out,
                                    __half* __restrict__ h, __half* __restrict__ l, int n4) {
    int i = blockIdx.x * blockDim.x + threadIdx.x;
    if (i >= n4) return;
    size_t stride4 = (size_t)n4;
    float4 v = ((const float4*)part)[i];
#pragma unroll
    for (int z = 1; z < NSPLIT; z++) {
        float4 w = ((const float4*)part)[z * stride4 + i];
        v.x += w.x; v.y += w.y; v.z += w.z; v.w += w.w;
    }
    ((float4*)out)[i] = v;
    if (DO_SPLIT) {
        float hx = __half2float(__float2half_rn(v.x));
        float hy = __half2float(__float2half_rn(v.y));
        float hz = __half2float(__float2half_rn(v.z));
        float hw = __half2float(__float2half_rn(v.w));
        ((__half2*)h)[i * 2] = __floats2half2_rn(hx, hy);
        ((__half2*)h)[i * 2 + 1] = __floats2half2_rn(hz, hw);
        ((__half2*)l)[i * 2] = __floats2half2_rn(v.x - hx, v.y - hy);
        ((__half2*)l)[i * 2 + 1] = __floats2half2_rn(v.z - hz, v.w - hw);
    }
}

template <int NSPLIT>
__global__ void reduce_h_kernel(const float* __restrict__ part, __half* __restrict__ out,
                                int n4) {
    int i = blockIdx.x * blockDim.x + threadIdx.x;
    if (i >= n4) return;
    size_t stride4 = (size_t)n4;
    float4 v = ((const float4*)part)[i];
#pragma unroll
    for (int z = 1; z < NSPLIT; z++) {
        float4 w = ((const float4*)part)[z * stride4 + i];
        v.x += w.x; v.y += w.y; v.z += w.z; v.w += w.w;
    }
    ((__half2*)out)[i * 2] = __floats2half2_rn(v.x, v.y);
    ((__half2*)out)[i * 2 + 1] = __floats2half2_rn(v.z, v.w);
}

// ---------------------------------------------------------------------------
// One-shot input split: fs, ft, w1, w2 -> (hi, lo) fp16, single launch
// ---------------------------------------------------------------------------
#define N4_FS (NROW * NFEAT / 4)
#define N4_W1 (NHID * NFEAT / 4)
#define N4_W2 (NCLASS * NHID / 4)

__global__ void split_all_kernel(const float* __restrict__ fs, const float* __restrict__ ft,
                                 const float* __restrict__ w1, const float* __restrict__ w2,
                                 __half* __restrict__ fsh, __half* __restrict__ fsl,
                                 __half* __restrict__ fth, __half* __restrict__ ftl,
                                 __half* __restrict__ w1h, __half* __restrict__ w1l,
                                 __half* __restrict__ w2h, __half* __restrict__ w2l) {
    int gi = blockIdx.x * blockDim.x + threadIdx.x;
    const float* src;
    __half *h, *l;
    int i;
    if (gi < N4_FS) {
        src = fs; h = fsh; l = fsl; i = gi;
    } else if (gi < 2 * N4_FS) {
        src = ft; h = fth; l = ftl; i = gi - N4_FS;
    } else if (gi < 2 * N4_FS + N4_W1) {
        src = w1; h = w1h; l = w1l; i = gi - 2 * N4_FS;
    } else if (gi < 2 * N4_FS + N4_W1 + N4_W2) {
        src = w2; h = w2h; l = w2l; i = gi - 2 * N4_FS - N4_W1;
    } else {
        return;
    }
    float4 v = ((const float4*)src)[i];
    float hx = __half2float(__float2half_rn(v.x));
    float hy = __half2float(__float2half_rn(v.y));
    float hz = __half2float(__float2half_rn(v.z));
    float hw = __half2float(__float2half_rn(v.w));
    ((__half2*)h)[i * 2] = __floats2half2_rn(hx, hy);
    ((__half2*)h)[i * 2 + 1] = __floats2half2_rn(hz, hw);
    ((__half2*)l)[i * 2] = __floats2half2_rn(v.x - hx, v.y - hy);
    ((__half2*)l)[i * 2 + 1] = __floats2half2_rn(v.z - hz, v.w - hw);
}

// ---------------------------------------------------------------------------
// Row softmax: fp32 logits -> fp16 normalized weights (512 threads)
// ---------------------------------------------------------------------------
__global__ void softmax_rows_kernel(const float* __restrict__ adj, __half* __restrict__ out,
                                    int N) {
    extern __shared__ float srow[];
    __shared__ float warp_red[16];
    __shared__ float bcast;

    const int tid = threadIdx.x;
    const int lane = tid & 31;
    const int wid = tid >> 5;
    const int nw = blockDim.x >> 5;
    const float* r = adj + (size_t)blockIdx.x * N;
    __half* o = out + (size_t)blockIdx.x * N;
    const int NV = N / 4;

    float mx = -INFINITY;
    for (int i = tid; i < NV; i += blockDim.x) {
        float4 v = ((const float4*)r)[i];
        ((float4*)srow)[i] = v;
        mx = fmaxf(mx, fmaxf(fmaxf(v.x, v.y), fmaxf(v.z, v.w)));
    }
#pragma unroll
    for (int off = 16; off > 0; off >>= 1) mx = fmaxf(mx, __shfl_xor_sync(0xffffffffu, mx, off));
    if (lane == 0) warp_red[wid] = mx;
    __syncthreads();
    if (tid == 0) {
        float m = warp_red[0];
        for (int w = 1; w < nw; w++) m = fmaxf(m, warp_red[w]);
        bcast = m;
    }
    __syncthreads();
    mx = bcast;
    __syncthreads();

    float sum = 0.0f;
    for (int i = tid; i < NV; i += blockDim.x) {
        float4 v = ((const float4*)srow)[i];
        v.x = __expf(v.x - mx); v.y = __expf(v.y - mx);
        v.z = __expf(v.z - mx); v.w = __expf(v.w - mx);
        ((float4*)srow)[i] = v;
        sum += v.x + v.y + v.z + v.w;
    }
#pragma unroll
    for (int off = 16; off > 0; off >>= 1) sum += __shfl_xor_sync(0xffffffffu, sum, off);
    if (lane == 0) warp_red[wid] = sum;
    __syncthreads();
    if (tid == 0) {
        float s = 0.0f;
        for (int w = 0; w < nw; w++) s += warp_red[w];
        bcast = 1.0f / s;
    }
    __syncthreads();
    float inv = bcast;

    for (int i = tid; i < NV; i += blockDim.x) {
        float4 v = ((float4*)srow)[i];
        ((__half2*)o)[i * 2] = __floats2half2_rn(v.x * inv, v.y * inv);
        ((__half2*)o)[i * 2 + 1] = __floats2half2_rn(v.z * inv, v.w * inv);
    }
}

// ---------------------------------------------------------------------------
extern "C" void kernel_launch(void* const* d_in, const int* in_sizes, int n_in,
                              void* d_out, int out_size) {
    const float* fs = (const float*)d_in[0];
    const float* ft = (const float*)d_in[1];
    const float* w1 = (const float*)d_in[2];
    const float* w2 = (const float*)d_in[3];

    float* x1 = (float*)d_out;
    float* x2 = (float*)d_out + (size_t)NROW * NHID;

    float *adj, *p1, *p2, *pY;
    __half *adjh, *fsh, *fsl, *fth, *ftl, *w1h, *w1l, *w2h, *w2l;
    __half *Y1T, *Y2T, *x1h, *x1l;
    cudaGetSymbolAddress((void**)&adj, g_adj);
    cudaGetSymbolAddress((void**)&adjh, g_adjh);
    cudaGetSymbolAddress((void**)&fsh, g_fsh);
    cudaGetSymbolAddress((void**)&fsl, g_fsl);
    cudaGetSymbolAddress((void**)&fth, g_fth);
    cudaGetSymbolAddress((void**)&ftl, g_ftl);
    cudaGetSymbolAddress((void**)&w1h, g_w1h);
    cudaGetSymbolAddress((void**)&w1l, g_w1l);
    cudaGetSymbolAddress((void**)&w2h, g_w2h);
    cudaGetSymbolAddress((void**)&w2l, g_w2l);
    cudaGetSymbolAddress((void**)&Y1T, g_Y1T);
    cudaGetSymbolAddress((void**)&Y2T, g_Y2T);
    cudaGetSymbolAddress((void**)&x1h, g_x1h);
    cudaGetSymbolAddress((void**)&x1l, g_x1l);
    cudaGetSymbolAddress((void**)&p1, g_p1);
    cudaGetSymbolAddress((void**)&p2, g_p2);
    cudaGetSymbolAddress((void**)&pY, g_pY);

    constexpr int SMEM_BIG = 3 * 61440;                     // hgemm3_256 (3-stage KT=32)
    constexpr int SMEM_3SK = 2 * 40960;                     // hgemm3_splitk (2-stage) = 81920
    constexpr int SMEM_SKW = 3 * (128 * 144 + 256 * 144);   // wide split-K
    constexpr int SMEM_SK = 3 * (2 * 128 * 144);            // narrow split-K
    cudaFuncSetAttribute(hgemm3_256_kernel,
                         cudaFuncAttributeMaxDynamicSharedMemorySize, SMEM_BIG);
    cudaFuncSetAttribute(hgemm3_splitk_kernel<KSPLITY>,
                         cudaFuncAttributeMaxDynamicSharedMemorySize, SMEM_3SK);
    cudaFuncSetAttribute(hgemm1_splitk_wide_kernel,
                         cudaFuncAttributeMaxDynamicSharedMemorySize, SMEM_SKW);
    cudaFuncSetAttribute(hgemm1_splitk_kernel<KSPLIT2>,
                         cudaFuncAttributeMaxDynamicSharedMemorySize, SMEM_SK);

    // ---- pre-pass: all input splits in one launch
    {
        int total = 2 * N4_FS + N4_W1 + N4_W2;
        split_all_kernel<<<(total + 255) / 256, 256>>>(
            fs, ft, w1, w2, fsh, fsl, fth, ftl, w1h, w1l, w2h, w2l);
    }

    // 1) S = fs @ ft^T  (3-term, 256x128x32 tiles, 3-stage, 512 threads)
    hgemm3_256_kernel<<<dim3(NROW / 128, NROW / 256), 512, SMEM_BIG>>>(
        fsh, fsl, fth, ftl, adj, NROW, NROW, NFEAT);

    // 2) softmax -> fp16 weights
    softmax_rows_kernel<<<NROW, 512, NROW * sizeof(float)>>>(adj, adjh, NROW);

    // 3) Y1T = w1 @ fs^T  [NHID, NROW]  (3-term, split-K 4, 2 CTAs/SM)
    hgemm3_splitk_kernel<KSPLITY>
        <<<dim3(NROW / 128, NHID / 128, KSPLITY), 256, SMEM_3SK>>>(
            w1h, w1l, fsh, fsl, pY, NHID, NROW, NFEAT);
    {
        int n4 = NHID * NROW / 4;
        reduce_h_kernel<KSPLITY><<<(n4 + 255) / 256, 256>>>(pY, Y1T, n4);
    }

    // 4) x1 = adjh @ Y1  (wide split-K; reduce + fused split)
    hgemm1_splitk_wide_kernel<<<dim3(NHID / 256, NROW / 128, KSPLIT), 512, SMEM_SKW>>>(
        adjh, Y1T, p1, NROW, NHID, NROW);
    {
        int n4 = NROW * NHID / 4;
        reduce_split_kernel<KSPLIT, 1><<<(n4 + 255) / 256, 256>>>(p1, x1, x1h, x1l, n4);
    }

    // 5) Y2T = w2 @ x1^T  [NCLASS, NROW]  (3-term, split-K 4, 2 CTAs/SM)
    hgemm3_splitk_kernel<KSPLITY>
        <<<dim3(NROW / 128, NCLASS / 128, KSPLITY), 256, SMEM_3SK>>>(
            w2h, w2l, x1h, x1l, pY, NCLASS, NROW, NHID);
    {
        int n4 = NCLASS * NROW / 4;
        reduce_h_kernel<KSPLITY><<<(n4 + 255) / 256, 256>>>(pY, Y2T, n4);
    }

    // 6) x2 = adjh @ Y2  (split-K depth 4; reduce)
    hgemm1_splitk_kernel<KSPLIT2><<<dim3(NCLASS / 128, NROW / 128, KSPLIT2), 256, SMEM_SK>>>(
        adjh, Y2T, p2, NROW, NCLASS, NROW);
    {
        int n4 = NROW * NCLASS / 4;
        reduce_split_kernel<KSPLIT2, 0><<<(n4 + 255) / 256, 256>>>(p2, x2, nullptr, nullptr, n4);
    }
}

// round 14
// speedup vs baseline: 1.0534x; 1.0534x over previous
#include <cuda_runtime.h>
#include <cuda_fp16.h>
#include <cstdint>
#include <math.h>

#define NROW 8192
#define NFEAT 512
#define NHID 256
#define NCLASS 128
#define KSPLIT 4
#define KSPLIT2 4

// ---------------------------------------------------------------------------
// Static device scratch (allocation-free rule)
// ---------------------------------------------------------------------------
__device__ __align__(16) float  g_adj[(size_t)NROW * NROW];     // fp32 logits
__device__ __align__(16) __half g_adjh[(size_t)NROW * NROW];    // fp16 softmax weights
__device__ __align__(16) __half g_fsh[(size_t)NROW * NFEAT];
__device__ __align__(16) __half g_fsl[(size_t)NROW * NFEAT];
__device__ __align__(16) __half g_fth[(size_t)NROW * NFEAT];
__device__ __align__(16) __half g_ftl[(size_t)NROW * NFEAT];
__device__ __align__(16) __half g_w1h[(size_t)NHID * NFEAT];
__device__ __align__(16) __half g_w1l[(size_t)NHID * NFEAT];
__device__ __align__(16) __half g_w2h[(size_t)NCLASS * NHID];
__device__ __align__(16) __half g_w2l[(size_t)NCLASS * NHID];
__device__ __align__(16) __half g_Y1T[(size_t)NHID * NROW];
__device__ __align__(16) __half g_Y2T[(size_t)NCLASS * NROW];
__device__ __align__(16) __half g_x1h[(size_t)NROW * NHID];
__device__ __align__(16) __half g_x1l[(size_t)NROW * NHID];
__device__ __align__(16) float  g_p1[(size_t)KSPLIT * NROW * NHID];
__device__ __align__(16) float  g_p2[(size_t)KSPLIT2 * NROW * NCLASS];

// ---------------------------------------------------------------------------
// PTX helpers (sm_80-era features; safe for the non-'a' PTX target)
// ---------------------------------------------------------------------------
__device__ __forceinline__ uint32_t smem_u32(const void* p) {
    uint32_t a;
    asm("{ .reg .u64 t; cvta.to.shared.u64 t, %1; cvt.u32.u64 %0, t; }" : "=r"(a) : "l"(p));
    return a;
}

#define CP_ASYNC16(dst, src) \
    asm volatile("cp.async.cg.shared.global [%0], [%1], 16;" :: "r"(dst), "l"(src))
#define CP_COMMIT() asm volatile("cp.async.commit_group;" ::: "memory")

template <int N>
__device__ __forceinline__ void cp_wait() {
    asm volatile("cp.async.wait_group %0;" :: "n"(N) : "memory");
}

__device__ __forceinline__ void ldsm4(uint32_t* r, uint32_t addr) {
    asm volatile("ldmatrix.sync.aligned.m8n8.x4.shared.b16 {%0,%1,%2,%3}, [%4];"
                 : "=r"(r[0]), "=r"(r[1]), "=r"(r[2]), "=r"(r[3]) : "r"(addr));
}

__device__ __forceinline__ void mma_f16(float* c, const uint32_t* a, uint32_t b0, uint32_t b1) {
    asm volatile(
        "mma.sync.aligned.m16n8k16.row.col.f32.f16.f16.f32 "
        "{%0,%1,%2,%3}, {%4,%5,%6,%7}, {%8,%9}, {%0,%1,%2,%3};"
        : "+f"(c[0]), "+f"(c[1]), "+f"(c[2]), "+f"(c[3])
        : "r"(a[0]), "r"(a[1]), "r"(a[2]), "r"(a[3]), "r"(b0), "r"(b1));
}

// ---------------------------------------------------------------------------
// Big 3-term GEMM (logits): C = A@B^T, 256x128x32 CTA tile, 512 threads
// (16 warps 4x4, warp tile 64x32), 3-stage cp.async, term-major MMA order.
// ---------------------------------------------------------------------------
__global__ void __launch_bounds__(512, 1)
hgemm3_256_kernel(const __half* __restrict__ Ah, const __half* __restrict__ Al,
                  const __half* __restrict__ Bh, const __half* __restrict__ Bl,
                  float* __restrict__ C, int M, int N, int K) {
    constexpr int PITCH = 80;
    constexpr int ATILE = 256 * PITCH;
    constexpr int BTILE = 128 * PITCH;
    constexpr int STG = 2 * ATILE + 2 * BTILE;
    constexpr int STAGES = 3;

    extern __shared__ char smem[];
    const uint32_t smb = smem_u32(smem);

    const int tid = threadIdx.x;
    const int wid = tid >> 5;
    const int lane = tid & 31;
    const int warp_m = wid >> 2;
    const int warp_n = wid & 3;
    const int bm = blockIdx.y * 256;
    const int bn = blockIdx.x * 128;

    const int ra = (lane & 7) + ((lane >> 3) & 1) * 8;
    const int ca = lane >> 4;
    const int rbx = (lane & 7) + ((lane >> 4) & 1) * 8;
    const int cbx = (lane >> 3) & 1;

    const int alr = tid >> 1, ahalf = tid & 1;
    const int blr = tid >> 2, bq = tid & 3;

    float acc[4][4][4];
#pragma unroll
    for (int i = 0; i < 4; i++)
#pragma unroll
        for (int j = 0; j < 4; j++)
#pragma unroll
            for (int q = 0; q < 4; q++) acc[i][j][q] = 0.0f;

    auto load_stage = [&](int buf, int kb) {
        uint32_t base = smb + buf * STG;
        const __half* pa = Ah + (size_t)(bm + alr) * K + kb;
        const __half* qa = Al + (size_t)(bm + alr) * K + kb;
        uint32_t rowa = base + alr * PITCH;
#pragma unroll
        for (int j = 0; j < 2; j++) {
            int ch = ahalf * 2 + j;
            CP_ASYNC16(rowa + ch * 16, pa + ch * 8);
            CP_ASYNC16(rowa + ATILE + ch * 16, qa + ch * 8);
        }
        const __half* pb = Bh + (size_t)(bn + blr) * K + kb;
        const __half* qb = Bl + (size_t)(bn + blr) * K + kb;
        uint32_t rowb = base + 2 * ATILE + blr * PITCH;
        CP_ASYNC16(rowb + bq * 16, pb + bq * 8);
        CP_ASYNC16(rowb + BTILE + bq * 16, qb + bq * 8);
    };

    const int niter = K / 32;

#pragma unroll
    for (int s = 0; s < STAGES - 1; s++) {
        if (s < niter) load_stage(s, s * 32);
        CP_COMMIT();
    }

    for (int it = 0; it < niter; it++) {
        cp_wait<STAGES - 2>();
        __syncthreads();

        const int buf = it % STAGES;
        const uint32_t aH = smb + buf * STG;
        const uint32_t aL = aH + ATILE;
        const uint32_t bH = aH + 2 * ATILE;
        const uint32_t bL = bH + BTILE;

#pragma unroll
        for (int ks = 0; ks < 2; ks++) {
            const uint32_t aco = (uint32_t)(2 * ks + ca) * 16;
            const uint32_t bco = (uint32_t)(2 * ks + cbx) * 16;

            uint32_t ah[4][4], al_[4][4];
#pragma unroll
            for (int mf = 0; mf < 4; mf++) {
                uint32_t ro = (uint32_t)(warp_m * 64 + mf * 16 + ra) * PITCH;
                ldsm4(ah[mf], aH + ro + aco);
                ldsm4(al_[mf], aL + ro + aco);
            }
#pragma unroll
            for (int nb = 0; nb < 2; nb++) {
                uint32_t ro = (uint32_t)(warp_n * 32 + nb * 16 + rbx) * PITCH;
                uint32_t bh[4], bl[4];
                ldsm4(bh, bH + ro + bco);
                ldsm4(bl, bL + ro + bco);
#pragma unroll
                for (int p = 0; p < 2; p++) {
                    const int nf = nb * 2 + p;
#pragma unroll
                    for (int mf = 0; mf < 4; mf++)
                        mma_f16(acc[mf][nf], ah[mf], bh[2 * p], bh[2 * p + 1]);
#pragma unroll
                    for (int mf = 0; mf < 4; mf++)
                        mma_f16(acc[mf][nf], ah[mf], bl[2 * p], bl[2 * p + 1]);
#pragma unroll
                    for (int mf = 0; mf < 4; mf++)
                        mma_f16(acc[mf][nf], al_[mf], bh[2 * p], bh[2 * p + 1]);
                }
            }
        }

        const int nidx = it + STAGES - 1;
        if (nidx < niter) load_stage(nidx % STAGES, nidx * 32);
        CP_COMMIT();
    }

    const int tr = lane >> 2;
    const int tc = lane & 3;
#pragma unroll
    for (int mf = 0; mf < 4; mf++) {
#pragma unroll
        for (int nf = 0; nf < 4; nf++) {
            int r0 = bm + warp_m * 64 + mf * 16 + tr;
            int col = bn + warp_n * 32 + nf * 8 + 2 * tc;
            *(float2*)(C + (size_t)r0 * N + col) = make_float2(acc[mf][nf][0], acc[mf][nf][1]);
            *(float2*)(C + (size_t)(r0 + 8) * N + col) =
                make_float2(acc[mf][nf][2], acc[mf][nf][3]);
        }
    }
}

// ---------------------------------------------------------------------------
// General fp16 HMMA GEMM (128x128 tiles, 256 threads, warp tile 64x32).
//   TERMS=3 / TERMS=1; EPI=0 fp32, EPI=2 fp16 hi.
// ---------------------------------------------------------------------------
template <int TERMS, int KT, int STAGES, int EPI>
__global__ void __launch_bounds__(256, 1)
hgemm_kernel(const __half* __restrict__ Ah, const __half* __restrict__ Al,
             const __half* __restrict__ Bh, const __half* __restrict__ Bl,
             float* __restrict__ C, __half* __restrict__ Ch,
             int M, int N, int K) {
    constexpr int CPR = KT / 8;
    constexpr int PITCH = (CPR + 1) * 16;
    constexpr int TILE = 128 * PITCH;
    constexpr int NTO = (TERMS == 3) ? 2 : 1;
    constexpr int STG = 2 * NTO * TILE;
    constexpr int HC = CPR / 2;

    extern __shared__ char smem[];
    const uint32_t smb = smem_u32(smem);

    const int tid = threadIdx.x;
    const int wid = tid >> 5;
    const int lane = tid & 31;
    const int warp_m = wid >> 2;
    const int warp_n = wid & 3;
    const int bm = blockIdx.y * 128;
    const int bn = blockIdx.x * 128;

    const int ra = (lane & 7) + ((lane >> 3) & 1) * 8;
    const int ca = lane >> 4;
    const int rbx = (lane & 7) + ((lane >> 4) & 1) * 8;
    const int cbx = (lane >> 3) & 1;

    const int lr = tid >> 1;
    const int lc0 = (tid & 1) * HC;

    float acc[4][4][4];
#pragma unroll
    for (int i = 0; i < 4; i++)
#pragma unroll
        for (int j = 0; j < 4; j++)
#pragma unroll
            for (int q = 0; q < 4; q++) acc[i][j][q] = 0.0f;

    auto load_stage = [&](int buf, int kb) {
        uint32_t rowd = smb + buf * STG + lr * PITCH;
        uint32_t bOff = NTO * TILE;
        const __half* pa = Ah + (size_t)(bm + lr) * K + kb;
        const __half* pb = Bh + (size_t)(bn + lr) * K + kb;
#pragma unroll
        for (int j = 0; j < HC; j++) {
            int ch = lc0 + j;
            CP_ASYNC16(rowd + ch * 16, pa + ch * 8);
            CP_ASYNC16(rowd + bOff + ch * 16, pb + ch * 8);
        }
        if (TERMS == 3) {
            const __half* qa = Al + (size_t)(bm + lr) * K + kb;
            const __half* qb = Bl + (size_t)(bn + lr) * K + kb;
#pragma unroll
            for (int j = 0; j < HC; j++) {
                int ch = lc0 + j;
                CP_ASYNC16(rowd + TILE + ch * 16, qa + ch * 8);
                CP_ASYNC16(rowd + bOff + TILE + ch * 16, qb + ch * 8);
            }
        }
    };

    const int niter = K / KT;

#pragma unroll
    for (int s = 0; s < STAGES - 1; s++) {
        if (s < niter) load_stage(s, s * KT);
        CP_COMMIT();
    }

    for (int it = 0; it < niter; it++) {
        cp_wait<STAGES - 2>();
        __syncthreads();

        const int buf = it % STAGES;
        const uint32_t aH = smb + buf * STG;
        const uint32_t aL = aH + TILE;
        const uint32_t bH = aH + NTO * TILE;
        const uint32_t bL = bH + TILE;

#pragma unroll
        for (int ks = 0; ks < KT / 16; ks++) {
            const uint32_t aco = (uint32_t)(2 * ks + ca) * 16;
            const uint32_t bco = (uint32_t)(2 * ks + cbx) * 16;

            uint32_t ah[4][4], al_[4][4];
#pragma unroll
            for (int mf = 0; mf < 4; mf++) {
                uint32_t ro = (uint32_t)(warp_m * 64 + mf * 16 + ra) * PITCH;
                ldsm4(ah[mf], aH + ro + aco);
                if (TERMS == 3) ldsm4(al_[mf], aL + ro + aco);
            }
#pragma unroll
            for (int nb = 0; nb < 2; nb++) {
                uint32_t ro = (uint32_t)(warp_n * 32 + nb * 16 + rbx) * PITCH;
                uint32_t bh[4], bl[4];
                ldsm4(bh, bH + ro + bco);
                if (TERMS == 3) ldsm4(bl, bL + ro + bco);
#pragma unroll
                for (int p = 0; p < 2; p++) {
                    const int nf = nb * 2 + p;
#pragma unroll
                    for (int mf = 0; mf < 4; mf++)
                        mma_f16(acc[mf][nf], ah[mf], bh[2 * p], bh[2 * p + 1]);
                    if (TERMS == 3) {
#pragma unroll
                        for (int mf = 0; mf < 4; mf++)
                            mma_f16(acc[mf][nf], ah[mf], bl[2 * p], bl[2 * p + 1]);
#pragma unroll
                        for (int mf = 0; mf < 4; mf++)
                            mma_f16(acc[mf][nf], al_[mf], bh[2 * p], bh[2 * p + 1]);
                    }
                }
            }
        }

        const int nidx = it + STAGES - 1;
        if (nidx < niter) load_stage(nidx % STAGES, nidx * KT);
        CP_COMMIT();
    }

    const int tr = lane >> 2;
    const int tc = lane & 3;
#pragma unroll
    for (int mf = 0; mf < 4; mf++) {
#pragma unroll
        for (int nf = 0; nf < 4; nf++) {
            int r0 = bm + warp_m * 64 + mf * 16 + tr;
            int col = bn + warp_n * 32 + nf * 8 + 2 * tc;
#pragma unroll
            for (int hrow = 0; hrow < 2; hrow++) {
                float v0 = acc[mf][nf][2 * hrow], v1 = acc[mf][nf][2 * hrow + 1];
                size_t o = (size_t)(r0 + hrow * 8) * N + col;
                if (EPI == 0) {
                    *(float2*)(C + o) = make_float2(v0, v1);
                } else {
                    *(__half2*)(Ch + o) = __floats2half2_rn(v0, v1);
                }
            }
        }
    }
}

// ---------------------------------------------------------------------------
// Split-K 1-term GEMM, wide: CTA tile 128(M) x 256(N) x 64, 512 threads
// (16 warps 2x8, warp tile 64x32). grid (N/256, M/128, KSPLIT)
// ---------------------------------------------------------------------------
__global__ void __launch_bounds__(512, 1)
hgemm1_splitk_wide_kernel(const __half* __restrict__ Ah, const __half* __restrict__ Bh,
                          float* __restrict__ Cpart, int M, int N, int K) {
    constexpr int KT = 64;
    constexpr int PITCH = 144;
    constexpr int ATILE = 128 * PITCH;
    constexpr int BTILE = 256 * PITCH;
    constexpr int STG = ATILE + BTILE;
    constexpr int STAGES = 3;

    extern __shared__ char smem[];
    const uint32_t smb = smem_u32(smem);

    const int tid = threadIdx.x;
    const int wid = tid >> 5;
    const int lane = tid & 31;
    const int warp_m = wid >> 3;
    const int warp_n = wid & 7;
    const int bm = blockIdx.y * 128;
    const int bn = blockIdx.x * 256;
    const int kbase = blockIdx.z * (K / KSPLIT);
    float* C = Cpart + (size_t)blockIdx.z * M * N;

    const int ra = (lane & 7) + ((lane >> 3) & 1) * 8;
    const int ca = lane >> 4;
    const int rbx = (lane & 7) + ((lane >> 4) & 1) * 8;
    const int cbx = (lane >> 3) & 1;

    const int alr = tid >> 2, aq = tid & 3;
    const int blr = tid >> 1, bhh = tid & 1;

    float acc[4][4][4];
#pragma unroll
    for (int i = 0; i < 4; i++)
#pragma unroll
        for (int j = 0; j < 4; j++)
#pragma unroll
            for (int q = 0; q < 4; q++) acc[i][j][q] = 0.0f;

    auto load_stage = [&](int buf, int kb) {
        uint32_t base = smb + buf * STG;
        const __half* pa = Ah + (size_t)(bm + alr) * K + kb;
        uint32_t rowa = base + alr * PITCH;
#pragma unroll
        for (int j = 0; j < 2; j++) {
            int ch = aq * 2 + j;
            CP_ASYNC16(rowa + ch * 16, pa + ch * 8);
        }
        const __half* pb = Bh + (size_t)(bn + blr) * K + kb;
        uint32_t rowb = base + ATILE + blr * PITCH;
#pragma unroll
        for (int j = 0; j < 4; j++) {
            int ch = bhh * 4 + j;
            CP_ASYNC16(rowb + ch * 16, pb + ch * 8);
        }
    };

    const int niter = (K / KSPLIT) / KT;

#pragma unroll
    for (int s = 0; s < STAGES - 1; s++) {
        if (s < niter) load_stage(s, kbase + s * KT);
        CP_COMMIT();
    }

    for (int it = 0; it < niter; it++) {
        cp_wait<STAGES - 2>();
        __syncthreads();

        const int buf = it % STAGES;
        const uint32_t aH = smb + buf * STG;
        const uint32_t bH = aH + ATILE;

#pragma unroll
        for (int ks = 0; ks < KT / 16; ks++) {
            const uint32_t aco = (uint32_t)(2 * ks + ca) * 16;
            const uint32_t bco = (uint32_t)(2 * ks + cbx) * 16;

            uint32_t ah[4][4];
#pragma unroll
            for (int mf = 0; mf < 4; mf++) {
                uint32_t ro = (uint32_t)(warp_m * 64 + mf * 16 + ra) * PITCH;
                ldsm4(ah[mf], aH + ro + aco);
            }
#pragma unroll
            for (int nb = 0; nb < 2; nb++) {
                uint32_t ro = (uint32_t)(warp_n * 32 + nb * 16 + rbx) * PITCH;
                uint32_t bh[4];
                ldsm4(bh, bH + ro + bco);
#pragma unroll
                for (int p = 0; p < 2; p++) {
                    const int nf = nb * 2 + p;
#pragma unroll
                    for (int mf = 0; mf < 4; mf++)
                        mma_f16(acc[mf][nf], ah[mf], bh[2 * p], bh[2 * p + 1]);
                }
            }
        }

        const int nidx = it + STAGES - 1;
        if (nidx < niter) load_stage(nidx % STAGES, kbase + nidx * KT);
        CP_COMMIT();
    }

    const int tr = lane >> 2;
    const int tc = lane & 3;
#pragma unroll
    for (int mf = 0; mf < 4; mf++) {
#pragma unroll
        for (int nf = 0; nf < 4; nf++) {
            int r0 = bm + warp_m * 64 + mf * 16 + tr;
            int col = bn + warp_n * 32 + nf * 8 + 2 * tc;
            *(float2*)(C + (size_t)r0 * N + col) = make_float2(acc[mf][nf][0], acc[mf][nf][1]);
            *(float2*)(C + (size_t)(r0 + 8) * N + col) =
                make_float2(acc[mf][nf][2], acc[mf][nf][3]);
        }
    }
}

// ---------------------------------------------------------------------------
// Split-K 1-term GEMM (128x128 tile, 256 threads); grid.z = NSPLIT.
// ---------------------------------------------------------------------------
template <int NSPLIT>
__global__ void __launch_bounds__(256, 1)
hgemm1_splitk_kernel(const __half* __restrict__ Ah, const __half* __restrict__ Bh,
                     float* __restrict__ Cpart, int M, int N, int K) {
    constexpr int KT = 64;
    constexpr int PITCH = 144;
    constexpr int TILE = 128 * PITCH;
    constexpr int STG = 2 * TILE;
    constexpr int STAGES = 3;
    constexpr int HC = 4;

    extern __shared__ char smem[];
    const uint32_t smb = smem_u32(smem);

    const int tid = threadIdx.x;
    const int wid = tid >> 5;
    const int lane = tid & 31;
    const int warp_m = wid >> 2;
    const int warp_n = wid & 3;
    const int bm = blockIdx.y * 128;
    const int bn = blockIdx.x * 128;
    const int kbase = blockIdx.z * (K / NSPLIT);
    float* C = Cpart + (size_t)blockIdx.z * M * N;

    const int ra = (lane & 7) + ((lane >> 3) & 1) * 8;
    const int ca = lane >> 4;
    const int rbx = (lane & 7) + ((lane >> 4) & 1) * 8;
    const int cbx = (lane >> 3) & 1;

    const int lr = tid >> 1;
    const int lc0 = (tid & 1) * HC;

    float acc[4][4][4];
#pragma unroll
    for (int i = 0; i < 4; i++)
#pragma unroll
        for (int j = 0; j < 4; j++)
#pragma unroll
            for (int q = 0; q < 4; q++) acc[i][j][q] = 0.0f;

    auto load_stage = [&](int buf, int kb) {
        uint32_t rowd = smb + buf * STG + lr * PITCH;
        const __half* pa = Ah + (size_t)(bm + lr) * K + kb;
        const __half* pb = Bh + (size_t)(bn + lr) * K + kb;
#pragma unroll
        for (int j = 0; j < HC; j++) {
            int ch = lc0 + j;
            CP_ASYNC16(rowd + ch * 16, pa + ch * 8);
            CP_ASYNC16(rowd + TILE + ch * 16, pb + ch * 8);
        }
    };

    const int niter = (K / NSPLIT) / KT;

#pragma unroll
    for (int s = 0; s < STAGES - 1; s++) {
        if (s < niter) load_stage(s, kbase + s * KT);
        CP_COMMIT();
    }

    for (int it = 0; it < niter; it++) {
        cp_wait<STAGES - 2>();
        __syncthreads();

        const int buf = it % STAGES;
        const uint32_t aH = smb + buf * STG;
        const uint32_t bH = aH + TILE;

#pragma unroll
        for (int ks = 0; ks < 4; ks++) {
            const uint32_t aco = (uint32_t)(2 * ks + ca) * 16;
            const uint32_t bco = (uint32_t)(2 * ks + cbx) * 16;

            uint32_t ah[4][4];
#pragma unroll
            for (int mf = 0; mf < 4; mf++) {
                uint32_t ro = (uint32_t)(warp_m * 64 + mf * 16 + ra) * PITCH;
                ldsm4(ah[mf], aH + ro + aco);
            }
#pragma unroll
            for (int nb = 0; nb < 2; nb++) {
                uint32_t ro = (uint32_t)(warp_n * 32 + nb * 16 + rbx) * PITCH;
                uint32_t bh[4];
                ldsm4(bh, bH + ro + bco);
#pragma unroll
                for (int p = 0; p < 2; p++) {
                    const int nf = nb * 2 + p;
#pragma unroll
                    for (int mf = 0; mf < 4; mf++)
                        mma_f16(acc[mf][nf], ah[mf], bh[2 * p], bh[2 * p + 1]);
                }
            }
        }

        const int nidx = it + STAGES - 1;
        if (nidx < niter) load_stage(nidx % STAGES, kbase + nidx * KT);
        CP_COMMIT();
    }

    const int tr = lane >> 2;
    const int tc = lane & 3;
#pragma unroll
    for (int mf = 0; mf < 4; mf++) {
#pragma unroll
        for (int nf = 0; nf < 4; nf++) {
            int r0 = bm + warp_m * 64 + mf * 16 + tr;
            int col = bn + warp_n * 32 + nf * 8 + 2 * tc;
            *(float2*)(C + (size_t)r0 * N + col) = make_float2(acc[mf][nf][0], acc[mf][nf][1]);
            *(float2*)(C + (size_t)(r0 + 8) * N + col) =
                make_float2(acc[mf][nf][2], acc[mf][nf][3]);
        }
    }
}

// ---------------------------------------------------------------------------
// Split-K reduction: sum NSPLIT partials -> fp32 out (+ optional hi/lo split)
// ---------------------------------------------------------------------------
template <int NSPLIT, int DO_SPLIT>
__global__ void reduce_split_kernel(const float* __restrict__ part, float* __restrict__ out,
                                    __half* __restrict__ h, __half* __restrict__ l, int n4) {
    int i = blockIdx.x * blockDim.x + threadIdx.x;
    if (i >= n4) return;
    size_t stride4 = (size_t)n4;
    float4 v = ((const float4*)part)[i];
#pragma unroll
    for (int z = 1; z < NSPLIT; z++) {
        float4 w = ((const float4*)part)[z * stride4 + i];
        v.x += w.x; v.y += w.y; v.z += w.z; v.w += w.w;
    }
    ((float4*)out)[i] = v;
    if (DO_SPLIT) {
        float hx = __half2float(__float2half_rn(v.x));
        float hy = __half2float(__float2half_rn(v.y));
        float hz = __half2float(__float2half_rn(v.z));
        float hw = __half2float(__float2half_rn(v.w));
        ((__half2*)h)[i * 2] = __floats2half2_rn(hx, hy);
        ((__half2*)h)[i * 2 + 1] = __floats2half2_rn(hz, hw);
        ((__half2*)l)[i * 2] = __floats2half2_rn(v.x - hx, v.y - hy);
        ((__half2*)l)[i * 2 + 1] = __floats2half2_rn(v.z - hz, v.w - hw);
    }
}

// ---------------------------------------------------------------------------
// One-shot input split: fs, ft, w1, w2 -> (hi, lo) fp16, single launch
// ---------------------------------------------------------------------------
#define N4_FS (NROW * NFEAT / 4)
#define N4_W1 (NHID * NFEAT / 4)
#define N4_W2 (NCLASS * NHID / 4)

__global__ void split_all_kernel(const float* __restrict__ fs, const float* __restrict__ ft,
                                 const float* __restrict__ w1, const float* __restrict__ w2,
                                 __half* __restrict__ fsh, __half* __restrict__ fsl,
                                 __half* __restrict__ fth, __half* __restrict__ ftl,
                                 __half* __restrict__ w1h, __half* __restrict__ w1l,
                                 __half* __restrict__ w2h, __half* __restrict__ w2l) {
    int gi = blockIdx.x * blockDim.x + threadIdx.x;
    const float* src;
    __half *h, *l;
    int i;
    if (gi < N4_FS) {
        src = fs; h = fsh; l = fsl; i = gi;
    } else if (gi < 2 * N4_FS) {
        src = ft; h = fth; l = ftl; i = gi - N4_FS;
    } else if (gi < 2 * N4_FS + N4_W1) {
        src = w1; h = w1h; l = w1l; i = gi - 2 * N4_FS;
    } else if (gi < 2 * N4_FS + N4_W1 + N4_W2) {
        src = w2; h = w2h; l = w2l; i = gi - 2 * N4_FS - N4_W1;
    } else {
        return;
    }
    float4 v = ((const float4*)src)[i];
    float hx = __half2float(__float2half_rn(v.x));
    float hy = __half2float(__float2half_rn(v.y));
    float hz = __half2float(__float2half_rn(v.z));
    float hw = __half2float(__float2half_rn(v.w));
    ((__half2*)h)[i * 2] = __floats2half2_rn(hx, hy);
    ((__half2*)h)[i * 2 + 1] = __floats2half2_rn(hz, hw);
    ((__half2*)l)[i * 2] = __floats2half2_rn(v.x - hx, v.y - hy);
    ((__half2*)l)[i * 2 + 1] = __floats2half2_rn(v.z - hz, v.w - hw);
}

// ---------------------------------------------------------------------------
// Row softmax: fp32 logits -> fp16 normalized weights (512 threads)
// ---------------------------------------------------------------------------
__global__ void softmax_rows_kernel(const float* __restrict__ adj, __half* __restrict__ out,
                                    int N) {
    extern __shared__ float srow[];
    __shared__ float warp_red[16];
    __shared__ float bcast;

    const int tid = threadIdx.x;
    const int lane = tid & 31;
    const int wid = tid >> 5;
    const int nw = blockDim.x >> 5;
    const float* r = adj + (size_t)blockIdx.x * N;
    __half* o = out + (size_t)blockIdx.x * N;
    const int NV = N / 4;

    float mx = -INFINITY;
    for (int i = tid; i < NV; i += blockDim.x) {
        float4 v = ((const float4*)r)[i];
        ((float4*)srow)[i] = v;
        mx = fmaxf(mx, fmaxf(fmaxf(v.x, v.y), fmaxf(v.z, v.w)));
    }
#pragma unroll
    for (int off = 16; off > 0; off >>= 1) mx = fmaxf(mx, __shfl_xor_sync(0xffffffffu, mx, off));
    if (lane == 0) warp_red[wid] = mx;
    __syncthreads();
    if (tid == 0) {
        float m = warp_red[0];
        for (int w = 1; w < nw; w++) m = fmaxf(m, warp_red[w]);
        bcast = m;
    }
    __syncthreads();
    mx = bcast;
    __syncthreads();

    float sum = 0.0f;
    for (int i = tid; i < NV; i += blockDim.x) {
        float4 v = ((const float4*)srow)[i];
        v.x = __expf(v.x - mx); v.y = __expf(v.y - mx);
        v.z = __expf(v.z - mx); v.w = __expf(v.w - mx);
        ((float4*)srow)[i] = v;
        sum += v.x + v.y + v.z + v.w;
    }
#pragma unroll
    for (int off = 16; off > 0; off >>= 1) sum += __shfl_xor_sync(0xffffffffu, sum, off);
    if (lane == 0) warp_red[wid] = sum;
    __syncthreads();
    if (tid == 0) {
        float s = 0.0f;
        for (int w = 0; w < nw; w++) s += warp_red[w];
        bcast = 1.0f / s;
    }
    __syncthreads();
    float inv = bcast;

    for (int i = tid; i < NV; i += blockDim.x) {
        float4 v = ((float4*)srow)[i];
        ((__half2*)o)[i * 2] = __floats2half2_rn(v.x * inv, v.y * inv);
        ((__half2*)o)[i * 2 + 1] = __floats2half2_rn(v.z * inv, v.w * inv);
    }
}

// ---------------------------------------------------------------------------
extern "C" void kernel_launch(void* const* d_in, const int* in_sizes, int n_in,
                              void* d_out, int out_size) {
    const float* fs = (const float*)d_in[0];
    const float* ft = (const float*)d_in[1];
    const float* w1 = (const float*)d_in[2];
    const float* w2 = (const float*)d_in[3];

    float* x1 = (float*)d_out;
    float* x2 = (float*)d_out + (size_t)NROW * NHID;

    float *adj, *p1, *p2;
    __half *adjh, *fsh, *fsl, *fth, *ftl, *w1h, *w1l, *w2h, *w2l;
    __half *Y1T, *Y2T, *x1h, *x1l;
    cudaGetSymbolAddress((void**)&adj, g_adj);
    cudaGetSymbolAddress((void**)&adjh, g_adjh);
    cudaGetSymbolAddress((void**)&fsh, g_fsh);
    cudaGetSymbolAddress((void**)&fsl, g_fsl);
    cudaGetSymbolAddress((void**)&fth, g_fth);
    cudaGetSymbolAddress((void**)&ftl, g_ftl);
    cudaGetSymbolAddress((void**)&w1h, g_w1h);
    cudaGetSymbolAddress((void**)&w1l, g_w1l);
    cudaGetSymbolAddress((void**)&w2h, g_w2h);
    cudaGetSymbolAddress((void**)&w2l, g_w2l);
    cudaGetSymbolAddress((void**)&Y1T, g_Y1T);
    cudaGetSymbolAddress((void**)&Y2T, g_Y2T);
    cudaGetSymbolAddress((void**)&x1h, g_x1h);
    cudaGetSymbolAddress((void**)&x1l, g_x1l);
    cudaGetSymbolAddress((void**)&p1, g_p1);
    cudaGetSymbolAddress((void**)&p2, g_p2);

    constexpr int SMEM_BIG = 3 * 61440;                     // hgemm3_256 (3-stage KT=32)
    constexpr int SMEM_SPLIT = 4 * (2 * 2 * 128 * 80);      // narrow 3-term (4-stage)
    constexpr int SMEM_SKW = 3 * (128 * 144 + 256 * 144);   // wide split-K
    constexpr int SMEM_SK = 3 * (2 * 128 * 144);            // narrow split-K
    cudaFuncSetAttribute(hgemm3_256_kernel,
                         cudaFuncAttributeMaxDynamicSharedMemorySize, SMEM_BIG);
    cudaFuncSetAttribute(hgemm_kernel<3, 32, 4, 2>,
                         cudaFuncAttributeMaxDynamicSharedMemorySize, SMEM_SPLIT);
    cudaFuncSetAttribute(hgemm1_splitk_wide_kernel,
                         cudaFuncAttributeMaxDynamicSharedMemorySize, SMEM_SKW);
    cudaFuncSetAttribute(hgemm1_splitk_kernel<KSPLIT2>,
                         cudaFuncAttributeMaxDynamicSharedMemorySize, SMEM_SK);

    // ---- pre-pass: all input splits in one launch
    {
        int total = 2 * N4_FS + N4_W1 + N4_W2;
        split_all_kernel<<<(total + 255) / 256, 256>>>(
            fs, ft, w1, w2, fsh, fsl, fth, ftl, w1h, w1l, w2h, w2l);
    }

    // 1) S = fs @ ft^T  (3-term, 256x128x32 tiles, 3-stage, 512 threads)
    hgemm3_256_kernel<<<dim3(NROW / 128, NROW / 256), 512, SMEM_BIG>>>(
        fsh, fsl, fth, ftl, adj, NROW, NROW, NFEAT);

    // 2) softmax -> fp16 weights
    softmax_rows_kernel<<<NROW, 512, NROW * sizeof(float)>>>(adj, adjh, NROW);

    // 3) Y1T = w1 @ fs^T  [NHID, NROW]  (3-term, fp16 hi out)
    hgemm_kernel<3, 32, 4, 2><<<dim3(NROW / 128, NHID / 128), 256, SMEM_SPLIT>>>(
        w1h, w1l, fsh, fsl, nullptr, Y1T, NHID, NROW, NFEAT);

    // 4) x1 = adjh @ Y1  (wide split-K; reduce + fused split)
    hgemm1_splitk_wide_kernel<<<dim3(NHID / 256, NROW / 128, KSPLIT), 512, SMEM_SKW>>>(
        adjh, Y1T, p1, NROW, NHID, NROW);
    {
        int n4 = NROW * NHID / 4;
        reduce_split_kernel<KSPLIT, 1><<<(n4 + 255) / 256, 256>>>(p1, x1, x1h, x1l, n4);
    }

    // 5) Y2T = w2 @ x1^T  [NCLASS, NROW]  (3-term, fp16 hi out)
    hgemm_kernel<3, 32, 4, 2><<<dim3(NROW / 128, NCLASS / 128), 256, SMEM_SPLIT>>>(
        w2h, w2l, x1h, x1l, nullptr, Y2T, NCLASS, NROW, NHID);

    // 6) x2 = adjh @ Y2  (split-K depth 4; reduce)
    hgemm1_splitk_kernel<KSPLIT2><<<dim3(NCLASS / 128, NROW / 128, KSPLIT2), 256, SMEM_SK>>>(
        adjh, Y2T, p2, NROW, NCLASS, NROW);
    {
        int n4 = NROW * NCLASS / 4;
        reduce_split_kernel<KSPLIT2, 0><<<(n4 + 255) / 256, 256>>>(p2, x2, nullptr, nullptr, n4);
    }
}

// round 15
// speedup vs baseline: 1.0616x; 1.0078x over previous
#include <cuda_runtime.h>
#include <cuda_fp16.h>
#include <cstdint>
#include <math.h>

#define NROW 8192
#define NFEAT 512
#define NHID 256
#define NCLASS 128
#define KSPLIT 4
#define KSPLIT2 4

// ---------------------------------------------------------------------------
// Static device scratch (allocation-free rule)
// ---------------------------------------------------------------------------
__device__ __align__(16) float  g_adj[(size_t)NROW * NROW];     // fp32 logits
__device__ __align__(16) __half g_adjh[(size_t)NROW * NROW];    // fp16 softmax weights
__device__ __align__(16) __half g_fsh[(size_t)NROW * NFEAT];
__device__ __align__(16) __half g_fsl[(size_t)NROW * NFEAT];
__device__ __align__(16) __half g_fth[(size_t)NROW * NFEAT];
__device__ __align__(16) __half g_ftl[(size_t)NROW * NFEAT];
__device__ __align__(16) __half g_w1h[(size_t)NHID * NFEAT];
__device__ __align__(16) __half g_w1l[(size_t)NHID * NFEAT];
__device__ __align__(16) __half g_w2h[(size_t)NCLASS * NHID];
__device__ __align__(16) __half g_w2l[(size_t)NCLASS * NHID];
__device__ __align__(16) __half g_Y1T[(size_t)NHID * NROW];
__device__ __align__(16) __half g_Y2T[(size_t)NCLASS * NROW];
__device__ __align__(16) __half g_x1h[(size_t)NROW * NHID];
__device__ __align__(16) __half g_x1l[(size_t)NROW * NHID];
__device__ __align__(16) float  g_p1[(size_t)KSPLIT * NROW * NHID];
__device__ __align__(16) float  g_p2[(size_t)KSPLIT2 * NROW * NCLASS];

// ---------------------------------------------------------------------------
// PTX helpers (sm_80-era features; safe for the non-'a' PTX target)
// ---------------------------------------------------------------------------
__device__ __forceinline__ uint32_t smem_u32(const void* p) {
    uint32_t a;
    asm("{ .reg .u64 t; cvta.to.shared.u64 t, %1; cvt.u32.u64 %0, t; }" : "=r"(a) : "l"(p));
    return a;
}

#define CP_ASYNC16(dst, src) \
    asm volatile("cp.async.cg.shared.global [%0], [%1], 16;" :: "r"(dst), "l"(src))
#define CP_COMMIT() asm volatile("cp.async.commit_group;" ::: "memory")

template <int N>
__device__ __forceinline__ void cp_wait() {
    asm volatile("cp.async.wait_group %0;" :: "n"(N) : "memory");
}

__device__ __forceinline__ void ldsm4(uint32_t* r, uint32_t addr) {
    asm volatile("ldmatrix.sync.aligned.m8n8.x4.shared.b16 {%0,%1,%2,%3}, [%4];"
                 : "=r"(r[0]), "=r"(r[1]), "=r"(r[2]), "=r"(r[3]) : "r"(addr));
}

__device__ __forceinline__ void mma_f16(float* c, const uint32_t* a, uint32_t b0, uint32_t b1) {
    asm volatile(
        "mma.sync.aligned.m16n8k16.row.col.f32.f16.f16.f32 "
        "{%0,%1,%2,%3}, {%4,%5,%6,%7}, {%8,%9}, {%0,%1,%2,%3};"
        : "+f"(c[0]), "+f"(c[1]), "+f"(c[2]), "+f"(c[3])
        : "r"(a[0]), "r"(a[1]), "r"(a[2]), "r"(a[3]), "r"(b0), "r"(b1));
}

// ---------------------------------------------------------------------------
// Big 3-term GEMM (logits): C = A@B^T, 256x128x32 CTA tile, 512 threads
// (16 warps 4x4, warp tile 64x32), 3-stage cp.async, term-major MMA order.
// ---------------------------------------------------------------------------
__global__ void __launch_bounds__(512, 1)
hgemm3_256_kernel(const __half* __restrict__ Ah, const __half* __restrict__ Al,
                  const __half* __restrict__ Bh, const __half* __restrict__ Bl,
                  float* __restrict__ C, int M, int N, int K) {
    constexpr int PITCH = 80;
    constexpr int ATILE = 256 * PITCH;
    constexpr int BTILE = 128 * PITCH;
    constexpr int STG = 2 * ATILE + 2 * BTILE;
    constexpr int STAGES = 3;

    extern __shared__ char smem[];
    const uint32_t smb = smem_u32(smem);

    const int tid = threadIdx.x;
    const int wid = tid >> 5;
    const int lane = tid & 31;
    const int warp_m = wid >> 2;
    const int warp_n = wid & 3;
    const int bm = blockIdx.y * 256;
    const int bn = blockIdx.x * 128;

    const int ra = (lane & 7) + ((lane >> 3) & 1) * 8;
    const int ca = lane >> 4;
    const int rbx = (lane & 7) + ((lane >> 4) & 1) * 8;
    const int cbx = (lane >> 3) & 1;

    const int alr = tid >> 1, ahalf = tid & 1;
    const int blr = tid >> 2, bq = tid & 3;

    float acc[4][4][4];
#pragma unroll
    for (int i = 0; i < 4; i++)
#pragma unroll
        for (int j = 0; j < 4; j++)
#pragma unroll
            for (int q = 0; q < 4; q++) acc[i][j][q] = 0.0f;

    auto load_stage = [&](int buf, int kb) {
        uint32_t base = smb + buf * STG;
        const __half* pa = Ah + (size_t)(bm + alr) * K + kb;
        const __half* qa = Al + (size_t)(bm + alr) * K + kb;
        uint32_t rowa = base + alr * PITCH;
#pragma unroll
        for (int j = 0; j < 2; j++) {
            int ch = ahalf * 2 + j;
            CP_ASYNC16(rowa + ch * 16, pa + ch * 8);
            CP_ASYNC16(rowa + ATILE + ch * 16, qa + ch * 8);
        }
        const __half* pb = Bh + (size_t)(bn + blr) * K + kb;
        const __half* qb = Bl + (size_t)(bn + blr) * K + kb;
        uint32_t rowb = base + 2 * ATILE + blr * PITCH;
        CP_ASYNC16(rowb + bq * 16, pb + bq * 8);
        CP_ASYNC16(rowb + BTILE + bq * 16, qb + bq * 8);
    };

    const int niter = K / 32;

#pragma unroll
    for (int s = 0; s < STAGES - 1; s++) {
        if (s < niter) load_stage(s, s * 32);
        CP_COMMIT();
    }

    for (int it = 0; it < niter; it++) {
        cp_wait<STAGES - 2>();
        __syncthreads();

        const int buf = it % STAGES;
        const uint32_t aH = smb + buf * STG;
        const uint32_t aL = aH + ATILE;
        const uint32_t bH = aH + 2 * ATILE;
        const uint32_t bL = bH + BTILE;

#pragma unroll
        for (int ks = 0; ks < 2; ks++) {
            const uint32_t aco = (uint32_t)(2 * ks + ca) * 16;
            const uint32_t bco = (uint32_t)(2 * ks + cbx) * 16;

            uint32_t ah[4][4], al_[4][4];
#pragma unroll
            for (int mf = 0; mf < 4; mf++) {
                uint32_t ro = (uint32_t)(warp_m * 64 + mf * 16 + ra) * PITCH;
                ldsm4(ah[mf], aH + ro + aco);
                ldsm4(al_[mf], aL + ro + aco);
            }
#pragma unroll
            for (int nb = 0; nb < 2; nb++) {
                uint32_t ro = (uint32_t)(warp_n * 32 + nb * 16 + rbx) * PITCH;
                uint32_t bh[4], bl[4];
                ldsm4(bh, bH + ro + bco);
                ldsm4(bl, bL + ro + bco);
#pragma unroll
                for (int p = 0; p < 2; p++) {
                    const int nf = nb * 2 + p;
#pragma unroll
                    for (int mf = 0; mf < 4; mf++)
                        mma_f16(acc[mf][nf], ah[mf], bh[2 * p], bh[2 * p + 1]);
#pragma unroll
                    for (int mf = 0; mf < 4; mf++)
                        mma_f16(acc[mf][nf], ah[mf], bl[2 * p], bl[2 * p + 1]);
#pragma unroll
                    for (int mf = 0; mf < 4; mf++)
                        mma_f16(acc[mf][nf], al_[mf], bh[2 * p], bh[2 * p + 1]);
                }
            }
        }

        const int nidx = it + STAGES - 1;
        if (nidx < niter) load_stage(nidx % STAGES, nidx * 32);
        CP_COMMIT();
    }

    const int tr = lane >> 2;
    const int tc = lane & 3;
#pragma unroll
    for (int mf = 0; mf < 4; mf++) {
#pragma unroll
        for (int nf = 0; nf < 4; nf++) {
            int r0 = bm + warp_m * 64 + mf * 16 + tr;
            int col = bn + warp_n * 32 + nf * 8 + 2 * tc;
            *(float2*)(C + (size_t)r0 * N + col) = make_float2(acc[mf][nf][0], acc[mf][nf][1]);
            *(float2*)(C + (size_t)(r0 + 8) * N + col) =
                make_float2(acc[mf][nf][2], acc[mf][nf][3]);
        }
    }
}

// ---------------------------------------------------------------------------
// General fp16 HMMA GEMM (128x128 tiles, 256 threads, warp tile 64x32).
//   TERMS=3 / TERMS=1; EPI=0 fp32, EPI=2 fp16 hi.
// ---------------------------------------------------------------------------
template <int TERMS, int KT, int STAGES, int EPI>
__global__ void __launch_bounds__(256, 1)
hgemm_kernel(const __half* __restrict__ Ah, const __half* __restrict__ Al,
             const __half* __restrict__ Bh, const __half* __restrict__ Bl,
             float* __restrict__ C, __half* __restrict__ Ch,
             int M, int N, int K) {
    constexpr int CPR = KT / 8;
    constexpr int PITCH = (CPR + 1) * 16;
    constexpr int TILE = 128 * PITCH;
    constexpr int NTO = (TERMS == 3) ? 2 : 1;
    constexpr int STG = 2 * NTO * TILE;
    constexpr int HC = CPR / 2;

    extern __shared__ char smem[];
    const uint32_t smb = smem_u32(smem);

    const int tid = threadIdx.x;
    const int wid = tid >> 5;
    const int lane = tid & 31;
    const int warp_m = wid >> 2;
    const int warp_n = wid & 3;
    const int bm = blockIdx.y * 128;
    const int bn = blockIdx.x * 128;

    const int ra = (lane & 7) + ((lane >> 3) & 1) * 8;
    const int ca = lane >> 4;
    const int rbx = (lane & 7) + ((lane >> 4) & 1) * 8;
    const int cbx = (lane >> 3) & 1;

    const int lr = tid >> 1;
    const int lc0 = (tid & 1) * HC;

    float acc[4][4][4];
#pragma unroll
    for (int i = 0; i < 4; i++)
#pragma unroll
        for (int j = 0; j < 4; j++)
#pragma unroll
            for (int q = 0; q < 4; q++) acc[i][j][q] = 0.0f;

    auto load_stage = [&](int buf, int kb) {
        uint32_t rowd = smb + buf * STG + lr * PITCH;
        uint32_t bOff = NTO * TILE;
        const __half* pa = Ah + (size_t)(bm + lr) * K + kb;
        const __half* pb = Bh + (size_t)(bn + lr) * K + kb;
#pragma unroll
        for (int j = 0; j < HC; j++) {
            int ch = lc0 + j;
            CP_ASYNC16(rowd + ch * 16, pa + ch * 8);
            CP_ASYNC16(rowd + bOff + ch * 16, pb + ch * 8);
        }
        if (TERMS == 3) {
            const __half* qa = Al + (size_t)(bm + lr) * K + kb;
            const __half* qb = Bl + (size_t)(bn + lr) * K + kb;
#pragma unroll
            for (int j = 0; j < HC; j++) {
                int ch = lc0 + j;
                CP_ASYNC16(rowd + TILE + ch * 16, qa + ch * 8);
                CP_ASYNC16(rowd + bOff + TILE + ch * 16, qb + ch * 8);
            }
        }
    };

    const int niter = K / KT;

#pragma unroll
    for (int s = 0; s < STAGES - 1; s++) {
        if (s < niter) load_stage(s, s * KT);
        CP_COMMIT();
    }

    for (int it = 0; it < niter; it++) {
        cp_wait<STAGES - 2>();
        __syncthreads();

        const int buf = it % STAGES;
        const uint32_t aH = smb + buf * STG;
        const uint32_t aL = aH + TILE;
        const uint32_t bH = aH + NTO * TILE;
        const uint32_t bL = bH + TILE;

#pragma unroll
        for (int ks = 0; ks < KT / 16; ks++) {
            const uint32_t aco = (uint32_t)(2 * ks + ca) * 16;
            const uint32_t bco = (uint32_t)(2 * ks + cbx) * 16;

            uint32_t ah[4][4], al_[4][4];
#pragma unroll
            for (int mf = 0; mf < 4; mf++) {
                uint32_t ro = (uint32_t)(warp_m * 64 + mf * 16 + ra) * PITCH;
                ldsm4(ah[mf], aH + ro + aco);
                if (TERMS == 3) ldsm4(al_[mf], aL + ro + aco);
            }
#pragma unroll
            for (int nb = 0; nb < 2; nb++) {
                uint32_t ro = (uint32_t)(warp_n * 32 + nb * 16 + rbx) * PITCH;
                uint32_t bh[4], bl[4];
                ldsm4(bh, bH + ro + bco);
                if (TERMS == 3) ldsm4(bl, bL + ro + bco);
#pragma unroll
                for (int p = 0; p < 2; p++) {
                    const int nf = nb * 2 + p;
#pragma unroll
                    for (int mf = 0; mf < 4; mf++)
                        mma_f16(acc[mf][nf], ah[mf], bh[2 * p], bh[2 * p + 1]);
                    if (TERMS == 3) {
#pragma unroll
                        for (int mf = 0; mf < 4; mf++)
                            mma_f16(acc[mf][nf], ah[mf], bl[2 * p], bl[2 * p + 1]);
#pragma unroll
                        for (int mf = 0; mf < 4; mf++)
                            mma_f16(acc[mf][nf], al_[mf], bh[2 * p], bh[2 * p + 1]);
                    }
                }
            }
        }

        const int nidx = it + STAGES - 1;
        if (nidx < niter) load_stage(nidx % STAGES, nidx * KT);
        CP_COMMIT();
    }

    const int tr = lane >> 2;
    const int tc = lane & 3;
#pragma unroll
    for (int mf = 0; mf < 4; mf++) {
#pragma unroll
        for (int nf = 0; nf < 4; nf++) {
            int r0 = bm + warp_m * 64 + mf * 16 + tr;
            int col = bn + warp_n * 32 + nf * 8 + 2 * tc;
#pragma unroll
            for (int hrow = 0; hrow < 2; hrow++) {
                float v0 = acc[mf][nf][2 * hrow], v1 = acc[mf][nf][2 * hrow + 1];
                size_t o = (size_t)(r0 + hrow * 8) * N + col;
                if (EPI == 0) {
                    *(float2*)(C + o) = make_float2(v0, v1);
                } else {
                    *(__half2*)(Ch + o) = __floats2half2_rn(v0, v1);
                }
            }
        }
    }
}

// ---------------------------------------------------------------------------
// Split-K 1-term GEMM, wide: CTA tile 128(M) x 256(N) x 64, 512 threads
// (16 warps 2x8, warp tile 64x32). grid (N/256, M/128, KSPLIT)
// ---------------------------------------------------------------------------
__global__ void __launch_bounds__(512, 1)
hgemm1_splitk_wide_kernel(const __half* __restrict__ Ah, const __half* __restrict__ Bh,
                          float* __restrict__ Cpart, int M, int N, int K) {
    constexpr int KT = 64;
    constexpr int PITCH = 144;
    constexpr int ATILE = 128 * PITCH;
    constexpr int BTILE = 256 * PITCH;
    constexpr int STG = ATILE + BTILE;
    constexpr int STAGES = 3;

    extern __shared__ char smem[];
    const uint32_t smb = smem_u32(smem);

    const int tid = threadIdx.x;
    const int wid = tid >> 5;
    const int lane = tid & 31;
    const int warp_m = wid >> 3;
    const int warp_n = wid & 7;
    const int bm = blockIdx.y * 128;
    const int bn = blockIdx.x * 256;
    const int kbase = blockIdx.z * (K / KSPLIT);
    float* C = Cpart + (size_t)blockIdx.z * M * N;

    const int ra = (lane & 7) + ((lane >> 3) & 1) * 8;
    const int ca = lane >> 4;
    const int rbx = (lane & 7) + ((lane >> 4) & 1) * 8;
    const int cbx = (lane >> 3) & 1;

    const int alr = tid >> 2, aq = tid & 3;
    const int blr = tid >> 1, bhh = tid & 1;

    float acc[4][4][4];
#pragma unroll
    for (int i = 0; i < 4; i++)
#pragma unroll
        for (int j = 0; j < 4; j++)
#pragma unroll
            for (int q = 0; q < 4; q++) acc[i][j][q] = 0.0f;

    auto load_stage = [&](int buf, int kb) {
        uint32_t base = smb + buf * STG;
        const __half* pa = Ah + (size_t)(bm + alr) * K + kb;
        uint32_t rowa = base + alr * PITCH;
#pragma unroll
        for (int j = 0; j < 2; j++) {
            int ch = aq * 2 + j;
            CP_ASYNC16(rowa + ch * 16, pa + ch * 8);
        }
        const __half* pb = Bh + (size_t)(bn + blr) * K + kb;
        uint32_t rowb = base + ATILE + blr * PITCH;
#pragma unroll
        for (int j = 0; j < 4; j++) {
            int ch = bhh * 4 + j;
            CP_ASYNC16(rowb + ch * 16, pb + ch * 8);
        }
    };

    const int niter = (K / KSPLIT) / KT;

#pragma unroll
    for (int s = 0; s < STAGES - 1; s++) {
        if (s < niter) load_stage(s, kbase + s * KT);
        CP_COMMIT();
    }

    for (int it = 0; it < niter; it++) {
        cp_wait<STAGES - 2>();
        __syncthreads();

        const int buf = it % STAGES;
        const uint32_t aH = smb + buf * STG;
        const uint32_t bH = aH + ATILE;

#pragma unroll
        for (int ks = 0; ks < KT / 16; ks++) {
            const uint32_t aco = (uint32_t)(2 * ks + ca) * 16;
            const uint32_t bco = (uint32_t)(2 * ks + cbx) * 16;

            uint32_t ah[4][4];
#pragma unroll
            for (int mf = 0; mf < 4; mf++) {
                uint32_t ro = (uint32_t)(warp_m * 64 + mf * 16 + ra) * PITCH;
                ldsm4(ah[mf], aH + ro + aco);
            }
#pragma unroll
            for (int nb = 0; nb < 2; nb++) {
                uint32_t ro = (uint32_t)(warp_n * 32 + nb * 16 + rbx) * PITCH;
                uint32_t bh[4];
                ldsm4(bh, bH + ro + bco);
#pragma unroll
                for (int p = 0; p < 2; p++) {
                    const int nf = nb * 2 + p;
#pragma unroll
                    for (int mf = 0; mf < 4; mf++)
                        mma_f16(acc[mf][nf], ah[mf], bh[2 * p], bh[2 * p + 1]);
                }
            }
        }

        const int nidx = it + STAGES - 1;
        if (nidx < niter) load_stage(nidx % STAGES, kbase + nidx * KT);
        CP_COMMIT();
    }

    const int tr = lane >> 2;
    const int tc = lane & 3;
#pragma unroll
    for (int mf = 0; mf < 4; mf++) {
#pragma unroll
        for (int nf = 0; nf < 4; nf++) {
            int r0 = bm + warp_m * 64 + mf * 16 + tr;
            int col = bn + warp_n * 32 + nf * 8 + 2 * tc;
            *(float2*)(C + (size_t)r0 * N + col) = make_float2(acc[mf][nf][0], acc[mf][nf][1]);
            *(float2*)(C + (size_t)(r0 + 8) * N + col) =
                make_float2(acc[mf][nf][2], acc[mf][nf][3]);
        }
    }
}

// ---------------------------------------------------------------------------
// Split-K 1-term GEMM (128x128 tile, 256 threads); grid.z = NSPLIT.
// ---------------------------------------------------------------------------
template <int NSPLIT>
__global__ void __launch_bounds__(256, 1)
hgemm1_splitk_kernel(const __half* __restrict__ Ah, const __half* __restrict__ Bh,
                     float* __restrict__ Cpart, int M, int N, int K) {
    constexpr int KT = 64;
    constexpr int PITCH = 144;
    constexpr int TILE = 128 * PITCH;
    constexpr int STG = 2 * TILE;
    constexpr int STAGES = 3;
    constexpr int HC = 4;

    extern __shared__ char smem[];
    const uint32_t smb = smem_u32(smem);

    const int tid = threadIdx.x;
    const int wid = tid >> 5;
    const int lane = tid & 31;
    const int warp_m = wid >> 2;
    const int warp_n = wid & 3;
    const int bm = blockIdx.y * 128;
    const int bn = blockIdx.x * 128;
    const int kbase = blockIdx.z * (K / NSPLIT);
    float* C = Cpart + (size_t)blockIdx.z * M * N;

    const int ra = (lane & 7) + ((lane >> 3) & 1) * 8;
    const int ca = lane >> 4;
    const int rbx = (lane & 7) + ((lane >> 4) & 1) * 8;
    const int cbx = (lane >> 3) & 1;

    const int lr = tid >> 1;
    const int lc0 = (tid & 1) * HC;

    float acc[4][4][4];
#pragma unroll
    for (int i = 0; i < 4; i++)
#pragma unroll
        for (int j = 0; j < 4; j++)
#pragma unroll
            for (int q = 0; q < 4; q++) acc[i][j][q] = 0.0f;

    auto load_stage = [&](int buf, int kb) {
        uint32_t rowd = smb + buf * STG + lr * PITCH;
        const __half* pa = Ah + (size_t)(bm + lr) * K + kb;
        const __half* pb = Bh + (size_t)(bn + lr) * K + kb;
#pragma unroll
        for (int j = 0; j < HC; j++) {
            int ch = lc0 + j;
            CP_ASYNC16(rowd + ch * 16, pa + ch * 8);
            CP_ASYNC16(rowd + TILE + ch * 16, pb + ch * 8);
        }
    };

    const int niter = (K / NSPLIT) / KT;

#pragma unroll
    for (int s = 0; s < STAGES - 1; s++) {
        if (s < niter) load_stage(s, kbase + s * KT);
        CP_COMMIT();
    }

    for (int it = 0; it < niter; it++) {
        cp_wait<STAGES - 2>();
        __syncthreads();

        const int buf = it % STAGES;
        const uint32_t aH = smb + buf * STG;
        const uint32_t bH = aH + TILE;

#pragma unroll
        for (int ks = 0; ks < 4; ks++) {
            const uint32_t aco = (uint32_t)(2 * ks + ca) * 16;
            const uint32_t bco = (uint32_t)(2 * ks + cbx) * 16;

            uint32_t ah[4][4];
#pragma unroll
            for (int mf = 0; mf < 4; mf++) {
                uint32_t ro = (uint32_t)(warp_m * 64 + mf * 16 + ra) * PITCH;
                ldsm4(ah[mf], aH + ro + aco);
            }
#pragma unroll
            for (int nb = 0; nb < 2; nb++) {
                uint32_t ro = (uint32_t)(warp_n * 32 + nb * 16 + rbx) * PITCH;
                uint32_t bh[4];
                ldsm4(bh, bH + ro + bco);
#pragma unroll
                for (int p = 0; p < 2; p++) {
                    const int nf = nb * 2 + p;
#pragma unroll
                    for (int mf = 0; mf < 4; mf++)
                        mma_f16(acc[mf][nf], ah[mf], bh[2 * p], bh[2 * p + 1]);
                }
            }
        }

        const int nidx = it + STAGES - 1;
        if (nidx < niter) load_stage(nidx % STAGES, kbase + nidx * KT);
        CP_COMMIT();
    }

    const int tr = lane >> 2;
    const int tc = lane & 3;
#pragma unroll
    for (int mf = 0; mf < 4; mf++) {
#pragma unroll
        for (int nf = 0; nf < 4; nf++) {
            int r0 = bm + warp_m * 64 + mf * 16 + tr;
            int col = bn + warp_n * 32 + nf * 8 + 2 * tc;
            *(float2*)(C + (size_t)r0 * N + col) = make_float2(acc[mf][nf][0], acc[mf][nf][1]);
            *(float2*)(C + (size_t)(r0 + 8) * N + col) =
                make_float2(acc[mf][nf][2], acc[mf][nf][3]);
        }
    }
}

// ---------------------------------------------------------------------------
// Split-K reduction: sum NSPLIT partials -> fp32 out (+ optional hi/lo split)
// ---------------------------------------------------------------------------
template <int NSPLIT, int DO_SPLIT>
__global__ void reduce_split_kernel(const float* __restrict__ part, float* __restrict__ out,
                                    __half* __restrict__ h, __half* __restrict__ l, int n4) {
    int i = blockIdx.x * blockDim.x + threadIdx.x;
    if (i >= n4) return;
    size_t stride4 = (size_t)n4;
    float4 v = ((const float4*)part)[i];
#pragma unroll
    for (int z = 1; z < NSPLIT; z++) {
        float4 w = ((const float4*)part)[z * stride4 + i];
        v.x += w.x; v.y += w.y; v.z += w.z; v.w += w.w;
    }
    ((float4*)out)[i] = v;
    if (DO_SPLIT) {
        float hx = __half2float(__float2half_rn(v.x));
        float hy = __half2float(__float2half_rn(v.y));
        float hz = __half2float(__float2half_rn(v.z));
        float hw = __half2float(__float2half_rn(v.w));
        ((__half2*)h)[i * 2] = __floats2half2_rn(hx, hy);
        ((__half2*)h)[i * 2 + 1] = __floats2half2_rn(hz, hw);
        ((__half2*)l)[i * 2] = __floats2half2_rn(v.x - hx, v.y - hy);
        ((__half2*)l)[i * 2 + 1] = __floats2half2_rn(v.z - hz, v.w - hw);
    }
}

// ---------------------------------------------------------------------------
// One-shot input split: fs, ft, w1, w2 -> (hi, lo) fp16, single launch
// ---------------------------------------------------------------------------
#define N4_FS (NROW * NFEAT / 4)
#define N4_W1 (NHID * NFEAT / 4)
#define N4_W2 (NCLASS * NHID / 4)

__global__ void split_all_kernel(const float* __restrict__ fs, const float* __restrict__ ft,
                                 const float* __restrict__ w1, const float* __restrict__ w2,
                                 __half* __restrict__ fsh, __half* __restrict__ fsl,
                                 __half* __restrict__ fth, __half* __restrict__ ftl,
                                 __half* __restrict__ w1h, __half* __restrict__ w1l,
                                 __half* __restrict__ w2h, __half* __restrict__ w2l) {
    int gi = blockIdx.x * blockDim.x + threadIdx.x;
    const float* src;
    __half *h, *l;
    int i;
    if (gi < N4_FS) {
        src = fs; h = fsh; l = fsl; i = gi;
    } else if (gi < 2 * N4_FS) {
        src = ft; h = fth; l = ftl; i = gi - N4_FS;
    } else if (gi < 2 * N4_FS + N4_W1) {
        src = w1; h = w1h; l = w1l; i = gi - 2 * N4_FS;
    } else if (gi < 2 * N4_FS + N4_W1 + N4_W2) {
        src = w2; h = w2h; l = w2l; i = gi - 2 * N4_FS - N4_W1;
    } else {
        return;
    }
    float4 v = ((const float4*)src)[i];
    float hx = __half2float(__float2half_rn(v.x));
    float hy = __half2float(__float2half_rn(v.y));
    float hz = __half2float(__float2half_rn(v.z));
    float hw = __half2float(__float2half_rn(v.w));
    ((__half2*)h)[i * 2] = __floats2half2_rn(hx, hy);
    ((__half2*)h)[i * 2 + 1] = __floats2half2_rn(hz, hw);
    ((__half2*)l)[i * 2] = __floats2half2_rn(v.x - hx, v.y - hy);
    ((__half2*)l)[i * 2 + 1] = __floats2half2_rn(v.z - hz, v.w - hw);
}

// ---------------------------------------------------------------------------
// Row softmax: fp32 logits -> fp16 normalized weights (512 threads)
// ---------------------------------------------------------------------------
__global__ void softmax_rows_kernel(const float* __restrict__ adj, __half* __restrict__ out,
                                    int N) {
    extern __shared__ float srow[];
    __shared__ float warp_red[16];
    __shared__ float bcast;

    const int tid = threadIdx.x;
    const int lane = tid & 31;
    const int wid = tid >> 5;
    const int nw = blockDim.x >> 5;
    const float* r = adj + (size_t)blockIdx.x * N;
    __half* o = out + (size_t)blockIdx.x * N;
    const int NV = N / 4;

    float mx = -INFINITY;
    for (int i = tid; i < NV; i += blockDim.x) {
        float4 v = ((const float4*)r)[i];
        ((float4*)srow)[i] = v;
        mx = fmaxf(mx, fmaxf(fmaxf(v.x, v.y), fmaxf(v.z, v.w)));
    }
#pragma unroll
    for (int off = 16; off > 0; off >>= 1) mx = fmaxf(mx, __shfl_xor_sync(0xffffffffu, mx, off));
    if (lane == 0) warp_red[wid] = mx;
    __syncthreads();
    if (tid == 0) {
        float m = warp_red[0];
        for (int w = 1; w < nw; w++) m = fmaxf(m, warp_red[w]);
        bcast = m;
    }
    __syncthreads();
    mx = bcast;
    __syncthreads();

    float sum = 0.0f;
    for (int i = tid; i < NV; i += blockDim.x) {
        float4 v = ((const float4*)srow)[i];
        v.x = __expf(v.x - mx); v.y = __expf(v.y - mx);
        v.z = __expf(v.z - mx); v.w = __expf(v.w - mx);
        ((float4*)srow)[i] = v;
        sum += v.x + v.y + v.z + v.w;
    }
#pragma unroll
    for (int off = 16; off > 0; off >>= 1) sum += __shfl_xor_sync(0xffffffffu, sum, off);
    if (lane == 0) warp_red[wid] = sum;
    __syncthreads();
    if (tid == 0) {
        float s = 0.0f;
        for (int w = 0; w < nw; w++) s += warp_red[w];
        bcast = 1.0f / s;
    }
    __syncthreads();
    float inv = bcast;

    for (int i = tid; i < NV; i += blockDim.x) {
        float4 v = ((float4*)srow)[i];
        ((__half2*)o)[i * 2] = __floats2half2_rn(v.x * inv, v.y * inv);
        ((__half2*)o)[i * 2 + 1] = __floats2half2_rn(v.z * inv, v.w * inv);
    }
}

// ---------------------------------------------------------------------------
extern "C" void kernel_launch(void* const* d_in, const int* in_sizes, int n_in,
                              void* d_out, int out_size) {
    const float* fs = (const float*)d_in[0];
    const float* ft = (const float*)d_in[1];
    const float* w1 = (const float*)d_in[2];
    const float* w2 = (const float*)d_in[3];

    float* x1 = (float*)d_out;
    float* x2 = (float*)d_out + (size_t)NROW * NHID;

    float *adj, *p1, *p2;
    __half *adjh, *fsh, *fsl, *fth, *ftl, *w1h, *w1l, *w2h, *w2l;
    __half *Y1T, *Y2T, *x1h, *x1l;
    cudaGetSymbolAddress((void**)&adj, g_adj);
    cudaGetSymbolAddress((void**)&adjh, g_adjh);
    cudaGetSymbolAddress((void**)&fsh, g_fsh);
    cudaGetSymbolAddress((void**)&fsl, g_fsl);
    cudaGetSymbolAddress((void**)&fth, g_fth);
    cudaGetSymbolAddress((void**)&ftl, g_ftl);
    cudaGetSymbolAddress((void**)&w1h, g_w1h);
    cudaGetSymbolAddress((void**)&w1l, g_w1l);
    cudaGetSymbolAddress((void**)&w2h, g_w2h);
    cudaGetSymbolAddress((void**)&w2l, g_w2l);
    cudaGetSymbolAddress((void**)&Y1T, g_Y1T);
    cudaGetSymbolAddress((void**)&Y2T, g_Y2T);
    cudaGetSymbolAddress((void**)&x1h, g_x1h);
    cudaGetSymbolAddress((void**)&x1l, g_x1l);
    cudaGetSymbolAddress((void**)&p1, g_p1);
    cudaGetSymbolAddress((void**)&p2, g_p2);

    constexpr int SMEM_BIG = 3 * 61440;                     // hgemm3_256 (3-stage KT=32)
    constexpr int SMEM_SPLIT = 4 * (2 * 2 * 128 * 80);      // narrow 3-term (4-stage)
    constexpr int SMEM_SKW = 3 * (128 * 144 + 256 * 144);   // wide split-K
    constexpr int SMEM_SK = 3 * (2 * 128 * 144);            // narrow split-K
    cudaFuncSetAttribute(hgemm3_256_kernel,
                         cudaFuncAttributeMaxDynamicSharedMemorySize, SMEM_BIG);
    cudaFuncSetAttribute(hgemm_kernel<3, 32, 4, 2>,
                         cudaFuncAttributeMaxDynamicSharedMemorySize, SMEM_SPLIT);
    cudaFuncSetAttribute(hgemm1_splitk_wide_kernel,
                         cudaFuncAttributeMaxDynamicSharedMemorySize, SMEM_SKW);
    cudaFuncSetAttribute(hgemm1_splitk_kernel<KSPLIT2>,
                         cudaFuncAttributeMaxDynamicSharedMemorySize, SMEM_SK);

    // Side stream + fork/join events (created per call, intentionally leaked:
    // kernel_launch runs only for the correctness pass and the capture pass).
    cudaStream_t s2;
    cudaEvent_t evFork, evJoin;
    cudaStreamCreateWithFlags(&s2, cudaStreamNonBlocking);
    cudaEventCreateWithFlags(&evFork, cudaEventDisableTiming);
    cudaEventCreateWithFlags(&evJoin, cudaEventDisableTiming);

    // ---- pre-pass: all input splits in one launch
    {
        int total = 2 * N4_FS + N4_W1 + N4_W2;
        split_all_kernel<<<(total + 255) / 256, 256>>>(
            fs, ft, w1, w2, fsh, fsl, fth, ftl, w1h, w1l, w2h, w2l);
    }

    // ---- fork: Y1T = w1 @ fs^T depends only on the splits -> side stream,
    //      overlapping with GEMM1 + softmax on the main stream.
    cudaEventRecord(evFork, 0);
    cudaStreamWaitEvent(s2, evFork, 0);
    hgemm_kernel<3, 32, 4, 2><<<dim3(NROW / 128, NHID / 128), 256, SMEM_SPLIT, s2>>>(
        w1h, w1l, fsh, fsl, nullptr, Y1T, NHID, NROW, NFEAT);
    cudaEventRecord(evJoin, s2);

    // 1) S = fs @ ft^T  (3-term, 256x128x32 tiles, 3-stage, 512 threads)
    hgemm3_256_kernel<<<dim3(NROW / 128, NROW / 256), 512, SMEM_BIG>>>(
        fsh, fsl, fth, ftl, adj, NROW, NROW, NFEAT);

    // 2) softmax -> fp16 weights
    softmax_rows_kernel<<<NROW, 512, NROW * sizeof(float)>>>(adj, adjh, NROW);

    // ---- join: x1 needs both adjh (main) and Y1T (side)
    cudaStreamWaitEvent(0, evJoin, 0);

    // 4) x1 = adjh @ Y1  (wide split-K; reduce + fused split)
    hgemm1_splitk_wide_kernel<<<dim3(NHID / 256, NROW / 128, KSPLIT), 512, SMEM_SKW>>>(
        adjh, Y1T, p1, NROW, NHID, NROW);
    {
        int n4 = NROW * NHID / 4;
        reduce_split_kernel<KSPLIT, 1><<<(n4 + 255) / 256, 256>>>(p1, x1, x1h, x1l, n4);
    }

    // 5) Y2T = w2 @ x1^T  [NCLASS, NROW]  (3-term, fp16 hi out)
    hgemm_kernel<3, 32, 4, 2><<<dim3(NROW / 128, NCLASS / 128), 256, SMEM_SPLIT>>>(
        w2h, w2l, x1h, x1l, nullptr, Y2T, NCLASS, NROW, NHID);

    // 6) x2 = adjh @ Y2  (split-K depth 4; reduce)
    hgemm1_splitk_kernel<KSPLIT2><<<dim3(NCLASS / 128, NROW / 128, KSPLIT2), 256, SMEM_SK>>>(
        adjh, Y2T, p2, NROW, NCLASS, NROW);
    {
        int n4 = NROW * NCLASS / 4;
        reduce_split_kernel<KSPLIT2, 0><<<(n4 + 255) / 256, 256>>>(p2, x2, nullptr, nullptr, n4);
    }
}

// round 16
// speedup vs baseline: 1.0773x; 1.0148x over previous
#include <cuda_runtime.h>
#include <cuda_fp16.h>
#include <cstdint>
#include <math.h>

#define NROW 8192
#define NFEAT 512
#define NHID 256
#define NCLASS 128
#define KSPLIT 4
#define KSPLIT2 4

// ---------------------------------------------------------------------------
// Static device scratch (allocation-free rule)
// ---------------------------------------------------------------------------
__device__ __align__(16) float  g_adj[(size_t)NROW * NROW];     // fp32 logits
__device__ __align__(16) __half g_adjh[(size_t)NROW * NROW];    // fp16 softmax weights
__device__ __align__(16) __half g_fsh[(size_t)NROW * NFEAT];
__device__ __align__(16) __half g_fsl[(size_t)NROW * NFEAT];
__device__ __align__(16) __half g_fth[(size_t)NROW * NFEAT];
__device__ __align__(16) __half g_ftl[(size_t)NROW * NFEAT];
__device__ __align__(16) __half g_w1h[(size_t)NHID * NFEAT];
__device__ __align__(16) __half g_w1l[(size_t)NHID * NFEAT];
__device__ __align__(16) __half g_w2h[(size_t)NCLASS * NHID];
__device__ __align__(16) __half g_w2l[(size_t)NCLASS * NHID];
__device__ __align__(16) __half g_Y1T[(size_t)NHID * NROW];
__device__ __align__(16) __half g_Y2T[(size_t)NCLASS * NROW];
__device__ __align__(16) __half g_x1h[(size_t)NROW * NHID];
__device__ __align__(16) __half g_x1l[(size_t)NROW * NHID];
__device__ __align__(16) float  g_p1[(size_t)KSPLIT * NROW * NHID];
__device__ __align__(16) float  g_p2[(size_t)KSPLIT2 * NROW * NCLASS];

// ---------------------------------------------------------------------------
// PTX helpers (sm_80-era features; safe for the non-'a' PTX target)
// ---------------------------------------------------------------------------
__device__ __forceinline__ uint32_t smem_u32(const void* p) {
    uint32_t a;
    asm("{ .reg .u64 t; cvta.to.shared.u64 t, %1; cvt.u32.u64 %0, t; }" : "=r"(a) : "l"(p));
    return a;
}

#define CP_ASYNC16(dst, src) \
    asm volatile("cp.async.cg.shared.global [%0], [%1], 16;" :: "r"(dst), "l"(src))
#define CP_COMMIT() asm volatile("cp.async.commit_group;" ::: "memory")

template <int N>
__device__ __forceinline__ void cp_wait() {
    asm volatile("cp.async.wait_group %0;" :: "n"(N) : "memory");
}

__device__ __forceinline__ void ldsm4(uint32_t* r, uint32_t addr) {
    asm volatile("ldmatrix.sync.aligned.m8n8.x4.shared.b16 {%0,%1,%2,%3}, [%4];"
                 : "=r"(r[0]), "=r"(r[1]), "=r"(r[2]), "=r"(r[3]) : "r"(addr));
}

__device__ __forceinline__ void mma_f16(float* c, const uint32_t* a, uint32_t b0, uint32_t b1) {
    asm volatile(
        "mma.sync.aligned.m16n8k16.row.col.f32.f16.f16.f32 "
        "{%0,%1,%2,%3}, {%4,%5,%6,%7}, {%8,%9}, {%0,%1,%2,%3};"
        : "+f"(c[0]), "+f"(c[1]), "+f"(c[2]), "+f"(c[3])
        : "r"(a[0]), "r"(a[1]), "r"(a[2]), "r"(a[3]), "r"(b0), "r"(b1));
}

// ---------------------------------------------------------------------------
// Big 3-term GEMM (logits): C = A@B^T, 256x128x32 CTA tile, 512 threads
// (16 warps 4x4, warp tile 64x32), 3-stage cp.async, term-major MMA order.
// ---------------------------------------------------------------------------
__global__ void __launch_bounds__(512, 1)
hgemm3_256_kernel(const __half* __restrict__ Ah, const __half* __restrict__ Al,
                  const __half* __restrict__ Bh, const __half* __restrict__ Bl,
                  float* __restrict__ C, int M, int N, int K) {
    constexpr int PITCH = 80;
    constexpr int ATILE = 256 * PITCH;
    constexpr int BTILE = 128 * PITCH;
    constexpr int STG = 2 * ATILE + 2 * BTILE;
    constexpr int STAGES = 3;

    extern __shared__ char smem[];
    const uint32_t smb = smem_u32(smem);

    const int tid = threadIdx.x;
    const int wid = tid >> 5;
    const int lane = tid & 31;
    const int warp_m = wid >> 2;
    const int warp_n = wid & 3;
    const int bm = blockIdx.y * 256;
    const int bn = blockIdx.x * 128;

    const int ra = (lane & 7) + ((lane >> 3) & 1) * 8;
    const int ca = lane >> 4;
    const int rbx = (lane & 7) + ((lane >> 4) & 1) * 8;
    const int cbx = (lane >> 3) & 1;

    const int alr = tid >> 1, ahalf = tid & 1;
    const int blr = tid >> 2, bq = tid & 3;

    float acc[4][4][4];
#pragma unroll
    for (int i = 0; i < 4; i++)
#pragma unroll
        for (int j = 0; j < 4; j++)
#pragma unroll
            for (int q = 0; q < 4; q++) acc[i][j][q] = 0.0f;

    auto load_stage = [&](int buf, int kb) {
        uint32_t base = smb + buf * STG;
        const __half* pa = Ah + (size_t)(bm + alr) * K + kb;
        const __half* qa = Al + (size_t)(bm + alr) * K + kb;
        uint32_t rowa = base + alr * PITCH;
#pragma unroll
        for (int j = 0; j < 2; j++) {
            int ch = ahalf * 2 + j;
            CP_ASYNC16(rowa + ch * 16, pa + ch * 8);
            CP_ASYNC16(rowa + ATILE + ch * 16, qa + ch * 8);
        }
        const __half* pb = Bh + (size_t)(bn + blr) * K + kb;
        const __half* qb = Bl + (size_t)(bn + blr) * K + kb;
        uint32_t rowb = base + 2 * ATILE + blr * PITCH;
        CP_ASYNC16(rowb + bq * 16, pb + bq * 8);
        CP_ASYNC16(rowb + BTILE + bq * 16, qb + bq * 8);
    };

    const int niter = K / 32;

#pragma unroll
    for (int s = 0; s < STAGES - 1; s++) {
        if (s < niter) load_stage(s, s * 32);
        CP_COMMIT();
    }

    for (int it = 0; it < niter; it++) {
        cp_wait<STAGES - 2>();
        __syncthreads();

        const int buf = it % STAGES;
        const uint32_t aH = smb + buf * STG;
        const uint32_t aL = aH + ATILE;
        const uint32_t bH = aH + 2 * ATILE;
        const uint32_t bL = bH + BTILE;

#pragma unroll
        for (int ks = 0; ks < 2; ks++) {
            const uint32_t aco = (uint32_t)(2 * ks + ca) * 16;
            const uint32_t bco = (uint32_t)(2 * ks + cbx) * 16;

            uint32_t ah[4][4], al_[4][4];
#pragma unroll
            for (int mf = 0; mf < 4; mf++) {
                uint32_t ro = (uint32_t)(warp_m * 64 + mf * 16 + ra) * PITCH;
                ldsm4(ah[mf], aH + ro + aco);
                ldsm4(al_[mf], aL + ro + aco);
            }
#pragma unroll
            for (int nb = 0; nb < 2; nb++) {
                uint32_t ro = (uint32_t)(warp_n * 32 + nb * 16 + rbx) * PITCH;
                uint32_t bh[4], bl[4];
                ldsm4(bh, bH + ro + bco);
                ldsm4(bl, bL + ro + bco);
#pragma unroll
                for (int p = 0; p < 2; p++) {
                    const int nf = nb * 2 + p;
#pragma unroll
                    for (int mf = 0; mf < 4; mf++)
                        mma_f16(acc[mf][nf], ah[mf], bh[2 * p], bh[2 * p + 1]);
#pragma unroll
                    for (int mf = 0; mf < 4; mf++)
                        mma_f16(acc[mf][nf], ah[mf], bl[2 * p], bl[2 * p + 1]);
#pragma unroll
                    for (int mf = 0; mf < 4; mf++)
                        mma_f16(acc[mf][nf], al_[mf], bh[2 * p], bh[2 * p + 1]);
                }
            }
        }

        const int nidx = it + STAGES - 1;
        if (nidx < niter) load_stage(nidx % STAGES, nidx * 32);
        CP_COMMIT();
    }

    const int tr = lane >> 2;
    const int tc = lane & 3;
#pragma unroll
    for (int mf = 0; mf < 4; mf++) {
#pragma unroll
        for (int nf = 0; nf < 4; nf++) {
            int r0 = bm + warp_m * 64 + mf * 16 + tr;
            int col = bn + warp_n * 32 + nf * 8 + 2 * tc;
            *(float2*)(C + (size_t)r0 * N + col) = make_float2(acc[mf][nf][0], acc[mf][nf][1]);
            *(float2*)(C + (size_t)(r0 + 8) * N + col) =
                make_float2(acc[mf][nf][2], acc[mf][nf][3]);
        }
    }
}

// ---------------------------------------------------------------------------
// General fp16 HMMA GEMM (128x128 tiles, 256 threads, warp tile 64x32).
//   TERMS=3 / TERMS=1; EPI=0 fp32, EPI=2 fp16 hi.
// ---------------------------------------------------------------------------
template <int TERMS, int KT, int STAGES, int EPI>
__global__ void __launch_bounds__(256, 1)
hgemm_kernel(const __half* __restrict__ Ah, const __half* __restrict__ Al,
             const __half* __restrict__ Bh, const __half* __restrict__ Bl,
             float* __restrict__ C, __half* __restrict__ Ch,
             int M, int N, int K) {
    constexpr int CPR = KT / 8;
    constexpr int PITCH = (CPR + 1) * 16;
    constexpr int TILE = 128 * PITCH;
    constexpr int NTO = (TERMS == 3) ? 2 : 1;
    constexpr int STG = 2 * NTO * TILE;
    constexpr int HC = CPR / 2;

    extern __shared__ char smem[];
    const uint32_t smb = smem_u32(smem);

    const int tid = threadIdx.x;
    const int wid = tid >> 5;
    const int lane = tid & 31;
    const int warp_m = wid >> 2;
    const int warp_n = wid & 3;
    const int bm = blockIdx.y * 128;
    const int bn = blockIdx.x * 128;

    const int ra = (lane & 7) + ((lane >> 3) & 1) * 8;
    const int ca = lane >> 4;
    const int rbx = (lane & 7) + ((lane >> 4) & 1) * 8;
    const int cbx = (lane >> 3) & 1;

    const int lr = tid >> 1;
    const int lc0 = (tid & 1) * HC;

    float acc[4][4][4];
#pragma unroll
    for (int i = 0; i < 4; i++)
#pragma unroll
        for (int j = 0; j < 4; j++)
#pragma unroll
            for (int q = 0; q < 4; q++) acc[i][j][q] = 0.0f;

    auto load_stage = [&](int buf, int kb) {
        uint32_t rowd = smb + buf * STG + lr * PITCH;
        uint32_t bOff = NTO * TILE;
        const __half* pa = Ah + (size_t)(bm + lr) * K + kb;
        const __half* pb = Bh + (size_t)(bn + lr) * K + kb;
#pragma unroll
        for (int j = 0; j < HC; j++) {
            int ch = lc0 + j;
            CP_ASYNC16(rowd + ch * 16, pa + ch * 8);
            CP_ASYNC16(rowd + bOff + ch * 16, pb + ch * 8);
        }
        if (TERMS == 3) {
            const __half* qa = Al + (size_t)(bm + lr) * K + kb;
            const __half* qb = Bl + (size_t)(bn + lr) * K + kb;
#pragma unroll
            for (int j = 0; j < HC; j++) {
                int ch = lc0 + j;
                CP_ASYNC16(rowd + TILE + ch * 16, qa + ch * 8);
                CP_ASYNC16(rowd + bOff + TILE + ch * 16, qb + ch * 8);
            }
        }
    };

    const int niter = K / KT;

#pragma unroll
    for (int s = 0; s < STAGES - 1; s++) {
        if (s < niter) load_stage(s, s * KT);
        CP_COMMIT();
    }

    for (int it = 0; it < niter; it++) {
        cp_wait<STAGES - 2>();
        __syncthreads();

        const int buf = it % STAGES;
        const uint32_t aH = smb + buf * STG;
        const uint32_t aL = aH + TILE;
        const uint32_t bH = aH + NTO * TILE;
        const uint32_t bL = bH + TILE;

#pragma unroll
        for (int ks = 0; ks < KT / 16; ks++) {
            const uint32_t aco = (uint32_t)(2 * ks + ca) * 16;
            const uint32_t bco = (uint32_t)(2 * ks + cbx) * 16;

            uint32_t ah[4][4], al_[4][4];
#pragma unroll
            for (int mf = 0; mf < 4; mf++) {
                uint32_t ro = (uint32_t)(warp_m * 64 + mf * 16 + ra) * PITCH;
                ldsm4(ah[mf], aH + ro + aco);
                if (TERMS == 3) ldsm4(al_[mf], aL + ro + aco);
            }
#pragma unroll
            for (int nb = 0; nb < 2; nb++) {
                uint32_t ro = (uint32_t)(warp_n * 32 + nb * 16 + rbx) * PITCH;
                uint32_t bh[4], bl[4];
                ldsm4(bh, bH + ro + bco);
                if (TERMS == 3) ldsm4(bl, bL + ro + bco);
#pragma unroll
                for (int p = 0; p < 2; p++) {
                    const int nf = nb * 2 + p;
#pragma unroll
                    for (int mf = 0; mf < 4; mf++)
                        mma_f16(acc[mf][nf], ah[mf], bh[2 * p], bh[2 * p + 1]);
                    if (TERMS == 3) {
#pragma unroll
                        for (int mf = 0; mf < 4; mf++)
                            mma_f16(acc[mf][nf], ah[mf], bl[2 * p], bl[2 * p + 1]);
#pragma unroll
                        for (int mf = 0; mf < 4; mf++)
                            mma_f16(acc[mf][nf], al_[mf], bh[2 * p], bh[2 * p + 1]);
                    }
                }
            }
        }

        const int nidx = it + STAGES - 1;
        if (nidx < niter) load_stage(nidx % STAGES, nidx * KT);
        CP_COMMIT();
    }

    const int tr = lane >> 2;
    const int tc = lane & 3;
#pragma unroll
    for (int mf = 0; mf < 4; mf++) {
#pragma unroll
        for (int nf = 0; nf < 4; nf++) {
            int r0 = bm + warp_m * 64 + mf * 16 + tr;
            int col = bn + warp_n * 32 + nf * 8 + 2 * tc;
#pragma unroll
            for (int hrow = 0; hrow < 2; hrow++) {
                float v0 = acc[mf][nf][2 * hrow], v1 = acc[mf][nf][2 * hrow + 1];
                size_t o = (size_t)(r0 + hrow * 8) * N + col;
                if (EPI == 0) {
                    *(float2*)(C + o) = make_float2(v0, v1);
                } else {
                    *(__half2*)(Ch + o) = __floats2half2_rn(v0, v1);
                }
            }
        }
    }
}

// ---------------------------------------------------------------------------
// Split-K 1-term GEMM, wide: CTA tile 128(M) x 256(N) x 64, 512 threads
// (16 warps 2x8, warp tile 64x32). grid (N/256, M/128, KSPLIT)
// ---------------------------------------------------------------------------
__global__ void __launch_bounds__(512, 1)
hgemm1_splitk_wide_kernel(const __half* __restrict__ Ah, const __half* __restrict__ Bh,
                          float* __restrict__ Cpart, int M, int N, int K) {
    constexpr int KT = 64;
    constexpr int PITCH = 144;
    constexpr int ATILE = 128 * PITCH;
    constexpr int BTILE = 256 * PITCH;
    constexpr int STG = ATILE + BTILE;
    constexpr int STAGES = 3;

    extern __shared__ char smem[];
    const uint32_t smb = smem_u32(smem);

    const int tid = threadIdx.x;
    const int wid = tid >> 5;
    const int lane = tid & 31;
    const int warp_m = wid >> 3;
    const int warp_n = wid & 7;
    const int bm = blockIdx.y * 128;
    const int bn = blockIdx.x * 256;
    const int kbase = blockIdx.z * (K / KSPLIT);
    float* C = Cpart + (size_t)blockIdx.z * M * N;

    const int ra = (lane & 7) + ((lane >> 3) & 1) * 8;
    const int ca = lane >> 4;
    const int rbx = (lane & 7) + ((lane >> 4) & 1) * 8;
    const int cbx = (lane >> 3) & 1;

    const int alr = tid >> 2, aq = tid & 3;
    const int blr = tid >> 1, bhh = tid & 1;

    float acc[4][4][4];
#pragma unroll
    for (int i = 0; i < 4; i++)
#pragma unroll
        for (int j = 0; j < 4; j++)
#pragma unroll
            for (int q = 0; q < 4; q++) acc[i][j][q] = 0.0f;

    auto load_stage = [&](int buf, int kb) {
        uint32_t base = smb + buf * STG;
        const __half* pa = Ah + (size_t)(bm + alr) * K + kb;
        uint32_t rowa = base + alr * PITCH;
#pragma unroll
        for (int j = 0; j < 2; j++) {
            int ch = aq * 2 + j;
            CP_ASYNC16(rowa + ch * 16, pa + ch * 8);
        }
        const __half* pb = Bh + (size_t)(bn + blr) * K + kb;
        uint32_t rowb = base + ATILE + blr * PITCH;
#pragma unroll
        for (int j = 0; j < 4; j++) {
            int ch = bhh * 4 + j;
            CP_ASYNC16(rowb + ch * 16, pb + ch * 8);
        }
    };

    const int niter = (K / KSPLIT) / KT;

#pragma unroll
    for (int s = 0; s < STAGES - 1; s++) {
        if (s < niter) load_stage(s, kbase + s * KT);
        CP_COMMIT();
    }

    for (int it = 0; it < niter; it++) {
        cp_wait<STAGES - 2>();
        __syncthreads();

        const int buf = it % STAGES;
        const uint32_t aH = smb + buf * STG;
        const uint32_t bH = aH + ATILE;

#pragma unroll
        for (int ks = 0; ks < KT / 16; ks++) {
            const uint32_t aco = (uint32_t)(2 * ks + ca) * 16;
            const uint32_t bco = (uint32_t)(2 * ks + cbx) * 16;

            uint32_t ah[4][4];
#pragma unroll
            for (int mf = 0; mf < 4; mf++) {
                uint32_t ro = (uint32_t)(warp_m * 64 + mf * 16 + ra) * PITCH;
                ldsm4(ah[mf], aH + ro + aco);
            }
#pragma unroll
            for (int nb = 0; nb < 2; nb++) {
                uint32_t ro = (uint32_t)(warp_n * 32 + nb * 16 + rbx) * PITCH;
                uint32_t bh[4];
                ldsm4(bh, bH + ro + bco);
#pragma unroll
                for (int p = 0; p < 2; p++) {
                    const int nf = nb * 2 + p;
#pragma unroll
                    for (int mf = 0; mf < 4; mf++)
                        mma_f16(acc[mf][nf], ah[mf], bh[2 * p], bh[2 * p + 1]);
                }
            }
        }

        const int nidx = it + STAGES - 1;
        if (nidx < niter) load_stage(nidx % STAGES, kbase + nidx * KT);
        CP_COMMIT();
    }

    const int tr = lane >> 2;
    const int tc = lane & 3;
#pragma unroll
    for (int mf = 0; mf < 4; mf++) {
#pragma unroll
        for (int nf = 0; nf < 4; nf++) {
            int r0 = bm + warp_m * 64 + mf * 16 + tr;
            int col = bn + warp_n * 32 + nf * 8 + 2 * tc;
            *(float2*)(C + (size_t)r0 * N + col) = make_float2(acc[mf][nf][0], acc[mf][nf][1]);
            *(float2*)(C + (size_t)(r0 + 8) * N + col) =
                make_float2(acc[mf][nf][2], acc[mf][nf][3]);
        }
    }
}

// ---------------------------------------------------------------------------
// Split-K 1-term GEMM (128x128 tile, 256 threads); grid.z = NSPLIT.
// ---------------------------------------------------------------------------
template <int NSPLIT>
__global__ void __launch_bounds__(256, 1)
hgemm1_splitk_kernel(const __half* __restrict__ Ah, const __half* __restrict__ Bh,
                     float* __restrict__ Cpart, int M, int N, int K) {
    constexpr int KT = 64;
    constexpr int PITCH = 144;
    constexpr int TILE = 128 * PITCH;
    constexpr int STG = 2 * TILE;
    constexpr int STAGES = 3;
    constexpr int HC = 4;

    extern __shared__ char smem[];
    const uint32_t smb = smem_u32(smem);

    const int tid = threadIdx.x;
    const int wid = tid >> 5;
    const int lane = tid & 31;
    const int warp_m = wid >> 2;
    const int warp_n = wid & 3;
    const int bm = blockIdx.y * 128;
    const int bn = blockIdx.x * 128;
    const int kbase = blockIdx.z * (K / NSPLIT);
    float* C = Cpart + (size_t)blockIdx.z * M * N;

    const int ra = (lane & 7) + ((lane >> 3) & 1) * 8;
    const int ca = lane >> 4;
    const int rbx = (lane & 7) + ((lane >> 4) & 1) * 8;
    const int cbx = (lane >> 3) & 1;

    const int lr = tid >> 1;
    const int lc0 = (tid & 1) * HC;

    float acc[4][4][4];
#pragma unroll
    for (int i = 0; i < 4; i++)
#pragma unroll
        for (int j = 0; j < 4; j++)
#pragma unroll
            for (int q = 0; q < 4; q++) acc[i][j][q] = 0.0f;

    auto load_stage = [&](int buf, int kb) {
        uint32_t rowd = smb + buf * STG + lr * PITCH;
        const __half* pa = Ah + (size_t)(bm + lr) * K + kb;
        const __half* pb = Bh + (size_t)(bn + lr) * K + kb;
#pragma unroll
        for (int j = 0; j < HC; j++) {
            int ch = lc0 + j;
            CP_ASYNC16(rowd + ch * 16, pa + ch * 8);
            CP_ASYNC16(rowd + TILE + ch * 16, pb + ch * 8);
        }
    };

    const int niter = (K / NSPLIT) / KT;

#pragma unroll
    for (int s = 0; s < STAGES - 1; s++) {
        if (s < niter) load_stage(s, kbase + s * KT);
        CP_COMMIT();
    }

    for (int it = 0; it < niter; it++) {
        cp_wait<STAGES - 2>();
        __syncthreads();

        const int buf = it % STAGES;
        const uint32_t aH = smb + buf * STG;
        const uint32_t bH = aH + TILE;

#pragma unroll
        for (int ks = 0; ks < 4; ks++) {
            const uint32_t aco = (uint32_t)(2 * ks + ca) * 16;
            const uint32_t bco = (uint32_t)(2 * ks + cbx) * 16;

            uint32_t ah[4][4];
#pragma unroll
            for (int mf = 0; mf < 4; mf++) {
                uint32_t ro = (uint32_t)(warp_m * 64 + mf * 16 + ra) * PITCH;
                ldsm4(ah[mf], aH + ro + aco);
            }
#pragma unroll
            for (int nb = 0; nb < 2; nb++) {
                uint32_t ro = (uint32_t)(warp_n * 32 + nb * 16 + rbx) * PITCH;
                uint32_t bh[4];
                ldsm4(bh, bH + ro + bco);
#pragma unroll
                for (int p = 0; p < 2; p++) {
                    const int nf = nb * 2 + p;
#pragma unroll
                    for (int mf = 0; mf < 4; mf++)
                        mma_f16(acc[mf][nf], ah[mf], bh[2 * p], bh[2 * p + 1]);
                }
            }
        }

        const int nidx = it + STAGES - 1;
        if (nidx < niter) load_stage(nidx % STAGES, kbase + nidx * KT);
        CP_COMMIT();
    }

    const int tr = lane >> 2;
    const int tc = lane & 3;
#pragma unroll
    for (int mf = 0; mf < 4; mf++) {
#pragma unroll
        for (int nf = 0; nf < 4; nf++) {
            int r0 = bm + warp_m * 64 + mf * 16 + tr;
            int col = bn + warp_n * 32 + nf * 8 + 2 * tc;
            *(float2*)(C + (size_t)r0 * N + col) = make_float2(acc[mf][nf][0], acc[mf][nf][1]);
            *(float2*)(C + (size_t)(r0 + 8) * N + col) =
                make_float2(acc[mf][nf][2], acc[mf][nf][3]);
        }
    }
}

// ---------------------------------------------------------------------------
// Split-K reduction: sum NSPLIT partials -> fp32 out (+ optional hi/lo split)
// ---------------------------------------------------------------------------
template <int NSPLIT, int DO_SPLIT>
__global__ void reduce_split_kernel(const float* __restrict__ part, float* __restrict__ out,
                                    __half* __restrict__ h, __half* __restrict__ l, int n4) {
    int i = blockIdx.x * blockDim.x + threadIdx.x;
    if (i >= n4) return;
    size_t stride4 = (size_t)n4;
    float4 v = ((const float4*)part)[i];
#pragma unroll
    for (int z = 1; z < NSPLIT; z++) {
        float4 w = ((const float4*)part)[z * stride4 + i];
        v.x += w.x; v.y += w.y; v.z += w.z; v.w += w.w;
    }
    ((float4*)out)[i] = v;
    if (DO_SPLIT) {
        float hx = __half2float(__float2half_rn(v.x));
        float hy = __half2float(__float2half_rn(v.y));
        float hz = __half2float(__float2half_rn(v.z));
        float hw = __half2float(__float2half_rn(v.w));
        ((__half2*)h)[i * 2] = __floats2half2_rn(hx, hy);
        ((__half2*)h)[i * 2 + 1] = __floats2half2_rn(hz, hw);
        ((__half2*)l)[i * 2] = __floats2half2_rn(v.x - hx, v.y - hy);
        ((__half2*)l)[i * 2 + 1] = __floats2half2_rn(v.z - hz, v.w - hw);
    }
}

// ---------------------------------------------------------------------------
// One-shot input split: fs, ft, w1, w2 -> (hi, lo) fp16, single launch
// ---------------------------------------------------------------------------
#define N4_FS (NROW * NFEAT / 4)
#define N4_W1 (NHID * NFEAT / 4)
#define N4_W2 (NCLASS * NHID / 4)

__global__ void split_all_kernel(const float* __restrict__ fs, const float* __restrict__ ft,
                                 const float* __restrict__ w1, const float* __restrict__ w2,
                                 __half* __restrict__ fsh, __half* __restrict__ fsl,
                                 __half* __restrict__ fth, __half* __restrict__ ftl,
                                 __half* __restrict__ w1h, __half* __restrict__ w1l,
                                 __half* __restrict__ w2h, __half* __restrict__ w2l) {
    int gi = blockIdx.x * blockDim.x + threadIdx.x;
    const float* src;
    __half *h, *l;
    int i;
    if (gi < N4_FS) {
        src = fs; h = fsh; l = fsl; i = gi;
    } else if (gi < 2 * N4_FS) {
        src = ft; h = fth; l = ftl; i = gi - N4_FS;
    } else if (gi < 2 * N4_FS + N4_W1) {
        src = w1; h = w1h; l = w1l; i = gi - 2 * N4_FS;
    } else if (gi < 2 * N4_FS + N4_W1 + N4_W2) {
        src = w2; h = w2h; l = w2l; i = gi - 2 * N4_FS - N4_W1;
    } else {
        return;
    }
    float4 v = ((const float4*)src)[i];
    float hx = __half2float(__float2half_rn(v.x));
    float hy = __half2float(__float2half_rn(v.y));
    float hz = __half2float(__float2half_rn(v.z));
    float hw = __half2float(__float2half_rn(v.w));
    ((__half2*)h)[i * 2] = __floats2half2_rn(hx, hy);
    ((__half2*)h)[i * 2 + 1] = __floats2half2_rn(hz, hw);
    ((__half2*)l)[i * 2] = __floats2half2_rn(v.x - hx, v.y - hy);
    ((__half2*)l)[i * 2 + 1] = __floats2half2_rn(v.z - hz, v.w - hw);
}

// ---------------------------------------------------------------------------
// Row softmax, register-resident: 8192 floats/row, 512 threads -> 4 float4
// per thread held in registers. No row smem buffer (kills the L1TEX bound).
// ---------------------------------------------------------------------------
__global__ void __launch_bounds__(512, 2)
softmax_rows_kernel(const float* __restrict__ adj, __half* __restrict__ out, int N) {
    __shared__ float warp_red[16];
    __shared__ float bcast;

    const int tid = threadIdx.x;
    const int lane = tid & 31;
    const int wid = tid >> 5;
    const float* r = adj + (size_t)blockIdx.x * N;
    __half* o = out + (size_t)blockIdx.x * N;

    // 4 float4 chunks per thread, block-strided
    float4 v[4];
#pragma unroll
    for (int j = 0; j < 4; j++) v[j] = ((const float4*)r)[tid + j * 512];

    float mx = -INFINITY;
#pragma unroll
    for (int j = 0; j < 4; j++)
        mx = fmaxf(mx, fmaxf(fmaxf(v[j].x, v[j].y), fmaxf(v[j].z, v[j].w)));
#pragma unroll
    for (int off = 16; off > 0; off >>= 1) mx = fmaxf(mx, __shfl_xor_sync(0xffffffffu, mx, off));
    if (lane == 0) warp_red[wid] = mx;
    __syncthreads();
    if (tid == 0) {
        float m = warp_red[0];
#pragma unroll
        for (int w = 1; w < 16; w++) m = fmaxf(m, warp_red[w]);
        bcast = m;
    }
    __syncthreads();
    mx = bcast;
    __syncthreads();

    float sum = 0.0f;
#pragma unroll
    for (int j = 0; j < 4; j++) {
        v[j].x = __expf(v[j].x - mx); v[j].y = __expf(v[j].y - mx);
        v[j].z = __expf(v[j].z - mx); v[j].w = __expf(v[j].w - mx);
        sum += v[j].x + v[j].y + v[j].z + v[j].w;
    }
#pragma unroll
    for (int off = 16; off > 0; off >>= 1) sum += __shfl_xor_sync(0xffffffffu, sum, off);
    if (lane == 0) warp_red[wid] = sum;
    __syncthreads();
    if (tid == 0) {
        float s = 0.0f;
#pragma unroll
        for (int w = 0; w < 16; w++) s += warp_red[w];
        bcast = 1.0f / s;
    }
    __syncthreads();
    const float inv = bcast;

#pragma unroll
    for (int j = 0; j < 4; j++) {
        int idx = tid + j * 512;
        ((__half2*)o)[idx * 2] = __floats2half2_rn(v[j].x * inv, v[j].y * inv);
        ((__half2*)o)[idx * 2 + 1] = __floats2half2_rn(v[j].z * inv, v[j].w * inv);
    }
}

// ---------------------------------------------------------------------------
extern "C" void kernel_launch(void* const* d_in, const int* in_sizes, int n_in,
                              void* d_out, int out_size) {
    const float* fs = (const float*)d_in[0];
    const float* ft = (const float*)d_in[1];
    const float* w1 = (const float*)d_in[2];
    const float* w2 = (const float*)d_in[3];

    float* x1 = (float*)d_out;
    float* x2 = (float*)d_out + (size_t)NROW * NHID;

    float *adj, *p1, *p2;
    __half *adjh, *fsh, *fsl, *fth, *ftl, *w1h, *w1l, *w2h, *w2l;
    __half *Y1T, *Y2T, *x1h, *x1l;
    cudaGetSymbolAddress((void**)&adj, g_adj);
    cudaGetSymbolAddress((void**)&adjh, g_adjh);
    cudaGetSymbolAddress((void**)&fsh, g_fsh);
    cudaGetSymbolAddress((void**)&fsl, g_fsl);
    cudaGetSymbolAddress((void**)&fth, g_fth);
    cudaGetSymbolAddress((void**)&ftl, g_ftl);
    cudaGetSymbolAddress((void**)&w1h, g_w1h);
    cudaGetSymbolAddress((void**)&w1l, g_w1l);
    cudaGetSymbolAddress((void**)&w2h, g_w2h);
    cudaGetSymbolAddress((void**)&w2l, g_w2l);
    cudaGetSymbolAddress((void**)&Y1T, g_Y1T);
    cudaGetSymbolAddress((void**)&Y2T, g_Y2T);
    cudaGetSymbolAddress((void**)&x1h, g_x1h);
    cudaGetSymbolAddress((void**)&x1l, g_x1l);
    cudaGetSymbolAddress((void**)&p1, g_p1);
    cudaGetSymbolAddress((void**)&p2, g_p2);

    constexpr int SMEM_BIG = 3 * 61440;                     // hgemm3_256 (3-stage KT=32)
    constexpr int SMEM_SPLIT = 4 * (2 * 2 * 128 * 80);      // narrow 3-term (4-stage)
    constexpr int SMEM_SKW = 3 * (128 * 144 + 256 * 144);   // wide split-K
    constexpr int SMEM_SK = 3 * (2 * 128 * 144);            // narrow split-K
    cudaFuncSetAttribute(hgemm3_256_kernel,
                         cudaFuncAttributeMaxDynamicSharedMemorySize, SMEM_BIG);
    cudaFuncSetAttribute(hgemm_kernel<3, 32, 4, 2>,
                         cudaFuncAttributeMaxDynamicSharedMemorySize, SMEM_SPLIT);
    cudaFuncSetAttribute(hgemm1_splitk_wide_kernel,
                         cudaFuncAttributeMaxDynamicSharedMemorySize, SMEM_SKW);
    cudaFuncSetAttribute(hgemm1_splitk_kernel<KSPLIT2>,
                         cudaFuncAttributeMaxDynamicSharedMemorySize, SMEM_SK);

    // Side stream + fork/join events (created per call, intentionally leaked:
    // kernel_launch runs only for the correctness pass and the capture pass).
    cudaStream_t s2;
    cudaEvent_t evFork, evJoin;
    cudaStreamCreateWithFlags(&s2, cudaStreamNonBlocking);
    cudaEventCreateWithFlags(&evFork, cudaEventDisableTiming);
    cudaEventCreateWithFlags(&evJoin, cudaEventDisableTiming);

    // ---- pre-pass: all input splits in one launch
    {
        int total = 2 * N4_FS + N4_W1 + N4_W2;
        split_all_kernel<<<(total + 255) / 256, 256>>>(
            fs, ft, w1, w2, fsh, fsl, fth, ftl, w1h, w1l, w2h, w2l);
    }

    // ---- fork: Y1T = w1 @ fs^T depends only on the splits -> side stream,
    //      overlapping with GEMM1 + softmax on the main stream.
    cudaEventRecord(evFork, 0);
    cudaStreamWaitEvent(s2, evFork, 0);
    hgemm_kernel<3, 32, 4, 2><<<dim3(NROW / 128, NHID / 128), 256, SMEM_SPLIT, s2>>>(
        w1h, w1l, fsh, fsl, nullptr, Y1T, NHID, NROW, NFEAT);
    cudaEventRecord(evJoin, s2);

    // 1) S = fs @ ft^T  (3-term, 256x128x32 tiles, 3-stage, 512 threads)
    hgemm3_256_kernel<<<dim3(NROW / 128, NROW / 256), 512, SMEM_BIG>>>(
        fsh, fsl, fth, ftl, adj, NROW, NROW, NFEAT);

    // 2) softmax -> fp16 weights (register-resident)
    softmax_rows_kernel<<<NROW, 512>>>(adj, adjh, NROW);

    // ---- join: x1 needs both adjh (main) and Y1T (side)
    cudaStreamWaitEvent(0, evJoin, 0);

    // 4) x1 = adjh @ Y1  (wide split-K; reduce + fused split)
    hgemm1_splitk_wide_kernel<<<dim3(NHID / 256, NROW / 128, KSPLIT), 512, SMEM_SKW>>>(
        adjh, Y1T, p1, NROW, NHID, NROW);
    {
        int n4 = NROW * NHID / 4;
        reduce_split_kernel<KSPLIT, 1><<<(n4 + 255) / 256, 256>>>(p1, x1, x1h, x1l, n4);
    }

    // 5) Y2T = w2 @ x1^T  [NCLASS, NROW]  (3-term, fp16 hi out)
    hgemm_kernel<3, 32, 4, 2><<<dim3(NROW / 128, NCLASS / 128), 256, SMEM_SPLIT>>>(
        w2h, w2l, x1h, x1l, nullptr, Y2T, NCLASS, NROW, NHID);

    // 6) x2 = adjh @ Y2  (split-K depth 4; reduce)
    hgemm1_splitk_kernel<KSPLIT2><<<dim3(NCLASS / 128, NROW / 128, KSPLIT2), 256, SMEM_SK>>>(
        adjh, Y2T, p2, NROW, NCLASS, NROW);
    {
        int n4 = NROW * NCLASS / 4;
        reduce_split_kernel<KSPLIT2, 0><<<(n4 + 255) / 256, 256>>>(p2, x2, nullptr, nullptr, n4);
    }
}

// round 17
// speedup vs baseline: 1.0873x; 1.0093x over previous
#include <cuda_runtime.h>
#include <cuda_fp16.h>
#include <cstdint>
#include <math.h>

#define NROW 8192
#define NFEAT 512
#define NHID 256
#define NCLASS 128
#define KSPLIT 4
#define KSPLIT2 4

// ---------------------------------------------------------------------------
// Static device scratch (allocation-free rule)
// ---------------------------------------------------------------------------
__device__ __align__(16) float  g_adj[(size_t)NROW * NROW];     // fp32 logits
__device__ __align__(16) __half g_adjh[(size_t)NROW * NROW];    // fp16 softmax weights
__device__ __align__(16) __half g_fsh[(size_t)NROW * NFEAT];
__device__ __align__(16) __half g_fsl[(size_t)NROW * NFEAT];
__device__ __align__(16) __half g_fth[(size_t)NROW * NFEAT];
__device__ __align__(16) __half g_ftl[(size_t)NROW * NFEAT];
__device__ __align__(16) __half g_w1h[(size_t)NHID * NFEAT];
__device__ __align__(16) __half g_w1l[(size_t)NHID * NFEAT];
__device__ __align__(16) __half g_w2h[(size_t)NCLASS * NHID];
__device__ __align__(16) __half g_w2l[(size_t)NCLASS * NHID];
__device__ __align__(16) __half g_Y1T[(size_t)NHID * NROW];
__device__ __align__(16) __half g_Y2T[(size_t)NCLASS * NROW];
__device__ __align__(16) __half g_x1h[(size_t)NROW * NHID];
__device__ __align__(16) __half g_x1l[(size_t)NROW * NHID];
__device__ __align__(16) float  g_p1[(size_t)KSPLIT * NROW * NHID];
__device__ __align__(16) float  g_p2[(size_t)KSPLIT2 * NROW * NCLASS];

// ---------------------------------------------------------------------------
// PTX helpers (sm_80-era features; safe for the non-'a' PTX target)
// ---------------------------------------------------------------------------
__device__ __forceinline__ uint32_t smem_u32(const void* p) {
    uint32_t a;
    asm("{ .reg .u64 t; cvta.to.shared.u64 t, %1; cvt.u32.u64 %0, t; }" : "=r"(a) : "l"(p));
    return a;
}

#define CP_ASYNC16(dst, src) \
    asm volatile("cp.async.cg.shared.global [%0], [%1], 16;" :: "r"(dst), "l"(src))
#define CP_COMMIT() asm volatile("cp.async.commit_group;" ::: "memory")

template <int N>
__device__ __forceinline__ void cp_wait() {
    asm volatile("cp.async.wait_group %0;" :: "n"(N) : "memory");
}

__device__ __forceinline__ void ldsm4(uint32_t* r, uint32_t addr) {
    asm volatile("ldmatrix.sync.aligned.m8n8.x4.shared.b16 {%0,%1,%2,%3}, [%4];"
                 : "=r"(r[0]), "=r"(r[1]), "=r"(r[2]), "=r"(r[3]) : "r"(addr));
}

__device__ __forceinline__ void mma_f16(float* c, const uint32_t* a, uint32_t b0, uint32_t b1) {
    asm volatile(
        "mma.sync.aligned.m16n8k16.row.col.f32.f16.f16.f32 "
        "{%0,%1,%2,%3}, {%4,%5,%6,%7}, {%8,%9}, {%0,%1,%2,%3};"
        : "+f"(c[0]), "+f"(c[1]), "+f"(c[2]), "+f"(c[3])
        : "r"(a[0]), "r"(a[1]), "r"(a[2]), "r"(a[3]), "r"(b0), "r"(b1));
}

// ---------------------------------------------------------------------------
// Big 3-term GEMM (logits): C = A@B^T, 256x128x32 CTA tile, 512 threads
// (16 warps 4x4, warp tile 64x32), 3-stage cp.async, term-major MMA order.
// ---------------------------------------------------------------------------
__global__ void __launch_bounds__(512, 1)
hgemm3_256_kernel(const __half* __restrict__ Ah, const __half* __restrict__ Al,
                  const __half* __restrict__ Bh, const __half* __restrict__ Bl,
                  float* __restrict__ C, int M, int N, int K) {
    constexpr int PITCH = 80;
    constexpr int ATILE = 256 * PITCH;
    constexpr int BTILE = 128 * PITCH;
    constexpr int STG = 2 * ATILE + 2 * BTILE;
    constexpr int STAGES = 3;

    extern __shared__ char smem[];
    const uint32_t smb = smem_u32(smem);

    const int tid = threadIdx.x;
    const int wid = tid >> 5;
    const int lane = tid & 31;
    const int warp_m = wid >> 2;
    const int warp_n = wid & 3;
    const int bm = blockIdx.y * 256;
    const int bn = blockIdx.x * 128;

    const int ra = (lane & 7) + ((lane >> 3) & 1) * 8;
    const int ca = lane >> 4;
    const int rbx = (lane & 7) + ((lane >> 4) & 1) * 8;
    const int cbx = (lane >> 3) & 1;

    const int alr = tid >> 1, ahalf = tid & 1;
    const int blr = tid >> 2, bq = tid & 3;

    float acc[4][4][4];
#pragma unroll
    for (int i = 0; i < 4; i++)
#pragma unroll
        for (int j = 0; j < 4; j++)
#pragma unroll
            for (int q = 0; q < 4; q++) acc[i][j][q] = 0.0f;

    auto load_stage = [&](int buf, int kb) {
        uint32_t base = smb + buf * STG;
        const __half* pa = Ah + (size_t)(bm + alr) * K + kb;
        const __half* qa = Al + (size_t)(bm + alr) * K + kb;
        uint32_t rowa = base + alr * PITCH;
#pragma unroll
        for (int j = 0; j < 2; j++) {
            int ch = ahalf * 2 + j;
            CP_ASYNC16(rowa + ch * 16, pa + ch * 8);
            CP_ASYNC16(rowa + ATILE + ch * 16, qa + ch * 8);
        }
        const __half* pb = Bh + (size_t)(bn + blr) * K + kb;
        const __half* qb = Bl + (size_t)(bn + blr) * K + kb;
        uint32_t rowb = base + 2 * ATILE + blr * PITCH;
        CP_ASYNC16(rowb + bq * 16, pb + bq * 8);
        CP_ASYNC16(rowb + BTILE + bq * 16, qb + bq * 8);
    };

    const int niter = K / 32;

#pragma unroll
    for (int s = 0; s < STAGES - 1; s++) {
        if (s < niter) load_stage(s, s * 32);
        CP_COMMIT();
    }

    for (int it = 0; it < niter; it++) {
        cp_wait<STAGES - 2>();
        __syncthreads();

        const int buf = it % STAGES;
        const uint32_t aH = smb + buf * STG;
        const uint32_t aL = aH + ATILE;
        const uint32_t bH = aH + 2 * ATILE;
        const uint32_t bL = bH + BTILE;

#pragma unroll
        for (int ks = 0; ks < 2; ks++) {
            const uint32_t aco = (uint32_t)(2 * ks + ca) * 16;
            const uint32_t bco = (uint32_t)(2 * ks + cbx) * 16;

            uint32_t ah[4][4], al_[4][4];
#pragma unroll
            for (int mf = 0; mf < 4; mf++) {
                uint32_t ro = (uint32_t)(warp_m * 64 + mf * 16 + ra) * PITCH;
                ldsm4(ah[mf], aH + ro + aco);
                ldsm4(al_[mf], aL + ro + aco);
            }
#pragma unroll
            for (int nb = 0; nb < 2; nb++) {
                uint32_t ro = (uint32_t)(warp_n * 32 + nb * 16 + rbx) * PITCH;
                uint32_t bh[4], bl[4];
                ldsm4(bh, bH + ro + bco);
                ldsm4(bl, bL + ro + bco);
#pragma unroll
                for (int p = 0; p < 2; p++) {
                    const int nf = nb * 2 + p;
#pragma unroll
                    for (int mf = 0; mf < 4; mf++)
                        mma_f16(acc[mf][nf], ah[mf], bh[2 * p], bh[2 * p + 1]);
#pragma unroll
                    for (int mf = 0; mf < 4; mf++)
                        mma_f16(acc[mf][nf], ah[mf], bl[2 * p], bl[2 * p + 1]);
#pragma unroll
                    for (int mf = 0; mf < 4; mf++)
                        mma_f16(acc[mf][nf], al_[mf], bh[2 * p], bh[2 * p + 1]);
                }
            }
        }

        const int nidx = it + STAGES - 1;
        if (nidx < niter) load_stage(nidx % STAGES, nidx * 32);
        CP_COMMIT();
    }

    const int tr = lane >> 2;
    const int tc = lane & 3;
#pragma unroll
    for (int mf = 0; mf < 4; mf++) {
#pragma unroll
        for (int nf = 0; nf < 4; nf++) {
            int r0 = bm + warp_m * 64 + mf * 16 + tr;
            int col = bn + warp_n * 32 + nf * 8 + 2 * tc;
            *(float2*)(C + (size_t)r0 * N + col) = make_float2(acc[mf][nf][0], acc[mf][nf][1]);
            *(float2*)(C + (size_t)(r0 + 8) * N + col) =
                make_float2(acc[mf][nf][2], acc[mf][nf][3]);
        }
    }
}

// ---------------------------------------------------------------------------
// General fp16 HMMA GEMM (128x128 tiles, 256 threads, warp tile 64x32).
//   TERMS=3 / TERMS=1; EPI=0 fp32, EPI=2 fp16 hi.
// ---------------------------------------------------------------------------
template <int TERMS, int KT, int STAGES, int EPI>
__global__ void __launch_bounds__(256, 1)
hgemm_kernel(const __half* __restrict__ Ah, const __half* __restrict__ Al,
             const __half* __restrict__ Bh, const __half* __restrict__ Bl,
             float* __restrict__ C, __half* __restrict__ Ch,
             int M, int N, int K) {
    constexpr int CPR = KT / 8;
    constexpr int PITCH = (CPR + 1) * 16;
    constexpr int TILE = 128 * PITCH;
    constexpr int NTO = (TERMS == 3) ? 2 : 1;
    constexpr int STG = 2 * NTO * TILE;
    constexpr int HC = CPR / 2;

    extern __shared__ char smem[];
    const uint32_t smb = smem_u32(smem);

    const int tid = threadIdx.x;
    const int wid = tid >> 5;
    const int lane = tid & 31;
    const int warp_m = wid >> 2;
    const int warp_n = wid & 3;
    const int bm = blockIdx.y * 128;
    const int bn = blockIdx.x * 128;

    const int ra = (lane & 7) + ((lane >> 3) & 1) * 8;
    const int ca = lane >> 4;
    const int rbx = (lane & 7) + ((lane >> 4) & 1) * 8;
    const int cbx = (lane >> 3) & 1;

    const int lr = tid >> 1;
    const int lc0 = (tid & 1) * HC;

    float acc[4][4][4];
#pragma unroll
    for (int i = 0; i < 4; i++)
#pragma unroll
        for (int j = 0; j < 4; j++)
#pragma unroll
            for (int q = 0; q < 4; q++) acc[i][j][q] = 0.0f;

    auto load_stage = [&](int buf, int kb) {
        uint32_t rowd = smb + buf * STG + lr * PITCH;
        uint32_t bOff = NTO * TILE;
        const __half* pa = Ah + (size_t)(bm + lr) * K + kb;
        const __half* pb = Bh + (size_t)(bn + lr) * K + kb;
#pragma unroll
        for (int j = 0; j < HC; j++) {
            int ch = lc0 + j;
            CP_ASYNC16(rowd + ch * 16, pa + ch * 8);
            CP_ASYNC16(rowd + bOff + ch * 16, pb + ch * 8);
        }
        if (TERMS == 3) {
            const __half* qa = Al + (size_t)(bm + lr) * K + kb;
            const __half* qb = Bl + (size_t)(bn + lr) * K + kb;
#pragma unroll
            for (int j = 0; j < HC; j++) {
                int ch = lc0 + j;
                CP_ASYNC16(rowd + TILE + ch * 16, qa + ch * 8);
                CP_ASYNC16(rowd + bOff + TILE + ch * 16, qb + ch * 8);
            }
        }
    };

    const int niter = K / KT;

#pragma unroll
    for (int s = 0; s < STAGES - 1; s++) {
        if (s < niter) load_stage(s, s * KT);
        CP_COMMIT();
    }

    for (int it = 0; it < niter; it++) {
        cp_wait<STAGES - 2>();
        __syncthreads();

        const int buf = it % STAGES;
        const uint32_t aH = smb + buf * STG;
        const uint32_t aL = aH + TILE;
        const uint32_t bH = aH + NTO * TILE;
        const uint32_t bL = bH + TILE;

#pragma unroll
        for (int ks = 0; ks < KT / 16; ks++) {
            const uint32_t aco = (uint32_t)(2 * ks + ca) * 16;
            const uint32_t bco = (uint32_t)(2 * ks + cbx) * 16;

            uint32_t ah[4][4], al_[4][4];
#pragma unroll
            for (int mf = 0; mf < 4; mf++) {
                uint32_t ro = (uint32_t)(warp_m * 64 + mf * 16 + ra) * PITCH;
                ldsm4(ah[mf], aH + ro + aco);
                if (TERMS == 3) ldsm4(al_[mf], aL + ro + aco);
            }
#pragma unroll
            for (int nb = 0; nb < 2; nb++) {
                uint32_t ro = (uint32_t)(warp_n * 32 + nb * 16 + rbx) * PITCH;
                uint32_t bh[4], bl[4];
                ldsm4(bh, bH + ro + bco);
                if (TERMS == 3) ldsm4(bl, bL + ro + bco);
#pragma unroll
                for (int p = 0; p < 2; p++) {
                    const int nf = nb * 2 + p;
#pragma unroll
                    for (int mf = 0; mf < 4; mf++)
                        mma_f16(acc[mf][nf], ah[mf], bh[2 * p], bh[2 * p + 1]);
                    if (TERMS == 3) {
#pragma unroll
                        for (int mf = 0; mf < 4; mf++)
                            mma_f16(acc[mf][nf], ah[mf], bl[2 * p], bl[2 * p + 1]);
#pragma unroll
                        for (int mf = 0; mf < 4; mf++)
                            mma_f16(acc[mf][nf], al_[mf], bh[2 * p], bh[2 * p + 1]);
                    }
                }
            }
        }

        const int nidx = it + STAGES - 1;
        if (nidx < niter) load_stage(nidx % STAGES, nidx * KT);
        CP_COMMIT();
    }

    const int tr = lane >> 2;
    const int tc = lane & 3;
#pragma unroll
    for (int mf = 0; mf < 4; mf++) {
#pragma unroll
        for (int nf = 0; nf < 4; nf++) {
            int r0 = bm + warp_m * 64 + mf * 16 + tr;
            int col = bn + warp_n * 32 + nf * 8 + 2 * tc;
#pragma unroll
            for (int hrow = 0; hrow < 2; hrow++) {
                float v0 = acc[mf][nf][2 * hrow], v1 = acc[mf][nf][2 * hrow + 1];
                size_t o = (size_t)(r0 + hrow * 8) * N + col;
                if (EPI == 0) {
                    *(float2*)(C + o) = make_float2(v0, v1);
                } else {
                    *(__half2*)(Ch + o) = __floats2half2_rn(v0, v1);
                }
            }
        }
    }
}

// ---------------------------------------------------------------------------
// Split-K 1-term GEMM, wide: CTA tile 128(M) x 256(N) x 64, 512 threads
// (16 warps 2x8, warp tile 64x32). grid (N/256, M/128, KSPLIT)
// ---------------------------------------------------------------------------
__global__ void __launch_bounds__(512, 1)
hgemm1_splitk_wide_kernel(const __half* __restrict__ Ah, const __half* __restrict__ Bh,
                          float* __restrict__ Cpart, int M, int N, int K) {
    constexpr int KT = 64;
    constexpr int PITCH = 144;
    constexpr int ATILE = 128 * PITCH;
    constexpr int BTILE = 256 * PITCH;
    constexpr int STG = ATILE + BTILE;
    constexpr int STAGES = 3;

    extern __shared__ char smem[];
    const uint32_t smb = smem_u32(smem);

    const int tid = threadIdx.x;
    const int wid = tid >> 5;
    const int lane = tid & 31;
    const int warp_m = wid >> 3;
    const int warp_n = wid & 7;
    const int bm = blockIdx.y * 128;
    const int bn = blockIdx.x * 256;
    const int kbase = blockIdx.z * (K / KSPLIT);
    float* C = Cpart + (size_t)blockIdx.z * M * N;

    const int ra = (lane & 7) + ((lane >> 3) & 1) * 8;
    const int ca = lane >> 4;
    const int rbx = (lane & 7) + ((lane >> 4) & 1) * 8;
    const int cbx = (lane >> 3) & 1;

    const int alr = tid >> 2, aq = tid & 3;
    const int blr = tid >> 1, bhh = tid & 1;

    float acc[4][4][4];
#pragma unroll
    for (int i = 0; i < 4; i++)
#pragma unroll
        for (int j = 0; j < 4; j++)
#pragma unroll
            for (int q = 0; q < 4; q++) acc[i][j][q] = 0.0f;

    auto load_stage = [&](int buf, int kb) {
        uint32_t base = smb + buf * STG;
        const __half* pa = Ah + (size_t)(bm + alr) * K + kb;
        uint32_t rowa = base + alr * PITCH;
#pragma unroll
        for (int j = 0; j < 2; j++) {
            int ch = aq * 2 + j;
            CP_ASYNC16(rowa + ch * 16, pa + ch * 8);
        }
        const __half* pb = Bh + (size_t)(bn + blr) * K + kb;
        uint32_t rowb = base + ATILE + blr * PITCH;
#pragma unroll
        for (int j = 0; j < 4; j++) {
            int ch = bhh * 4 + j;
            CP_ASYNC16(rowb + ch * 16, pb + ch * 8);
        }
    };

    const int niter = (K / KSPLIT) / KT;

#pragma unroll
    for (int s = 0; s < STAGES - 1; s++) {
        if (s < niter) load_stage(s, kbase + s * KT);
        CP_COMMIT();
    }

    for (int it = 0; it < niter; it++) {
        cp_wait<STAGES - 2>();
        __syncthreads();

        const int buf = it % STAGES;
        const uint32_t aH = smb + buf * STG;
        const uint32_t bH = aH + ATILE;

#pragma unroll
        for (int ks = 0; ks < KT / 16; ks++) {
            const uint32_t aco = (uint32_t)(2 * ks + ca) * 16;
            const uint32_t bco = (uint32_t)(2 * ks + cbx) * 16;

            uint32_t ah[4][4];
#pragma unroll
            for (int mf = 0; mf < 4; mf++) {
                uint32_t ro = (uint32_t)(warp_m * 64 + mf * 16 + ra) * PITCH;
                ldsm4(ah[mf], aH + ro + aco);
            }
#pragma unroll
            for (int nb = 0; nb < 2; nb++) {
                uint32_t ro = (uint32_t)(warp_n * 32 + nb * 16 + rbx) * PITCH;
                uint32_t bh[4];
                ldsm4(bh, bH + ro + bco);
#pragma unroll
                for (int p = 0; p < 2; p++) {
                    const int nf = nb * 2 + p;
#pragma unroll
                    for (int mf = 0; mf < 4; mf++)
                        mma_f16(acc[mf][nf], ah[mf], bh[2 * p], bh[2 * p + 1]);
                }
            }
        }

        const int nidx = it + STAGES - 1;
        if (nidx < niter) load_stage(nidx % STAGES, kbase + nidx * KT);
        CP_COMMIT();
    }

    const int tr = lane >> 2;
    const int tc = lane & 3;
#pragma unroll
    for (int mf = 0; mf < 4; mf++) {
#pragma unroll
        for (int nf = 0; nf < 4; nf++) {
            int r0 = bm + warp_m * 64 + mf * 16 + tr;
            int col = bn + warp_n * 32 + nf * 8 + 2 * tc;
            *(float2*)(C + (size_t)r0 * N + col) = make_float2(acc[mf][nf][0], acc[mf][nf][1]);
            *(float2*)(C + (size_t)(r0 + 8) * N + col) =
                make_float2(acc[mf][nf][2], acc[mf][nf][3]);
        }
    }
}

// ---------------------------------------------------------------------------
// Split-K 1-term GEMM (128x128 tile, 256 threads); grid.z = NSPLIT.
// ---------------------------------------------------------------------------
template <int NSPLIT>
__global__ void __launch_bounds__(256, 1)
hgemm1_splitk_kernel(const __half* __restrict__ Ah, const __half* __restrict__ Bh,
                     float* __restrict__ Cpart, int M, int N, int K) {
    constexpr int KT = 64;
    constexpr int PITCH = 144;
    constexpr int TILE = 128 * PITCH;
    constexpr int STG = 2 * TILE;
    constexpr int STAGES = 3;
    constexpr int HC = 4;

    extern __shared__ char smem[];
    const uint32_t smb = smem_u32(smem);

    const int tid = threadIdx.x;
    const int wid = tid >> 5;
    const int lane = tid & 31;
    const int warp_m = wid >> 2;
    const int warp_n = wid & 3;
    const int bm = blockIdx.y * 128;
    const int bn = blockIdx.x * 128;
    const int kbase = blockIdx.z * (K / NSPLIT);
    float* C = Cpart + (size_t)blockIdx.z * M * N;

    const int ra = (lane & 7) + ((lane >> 3) & 1) * 8;
    const int ca = lane >> 4;
    const int rbx = (lane & 7) + ((lane >> 4) & 1) * 8;
    const int cbx = (lane >> 3) & 1;

    const int lr = tid >> 1;
    const int lc0 = (tid & 1) * HC;

    float acc[4][4][4];
#pragma unroll
    for (int i = 0; i < 4; i++)
#pragma unroll
        for (int j = 0; j < 4; j++)
#pragma unroll
            for (int q = 0; q < 4; q++) acc[i][j][q] = 0.0f;

    auto load_stage = [&](int buf, int kb) {
        uint32_t rowd = smb + buf * STG + lr * PITCH;
        const __half* pa = Ah + (size_t)(bm + lr) * K + kb;
        const __half* pb = Bh + (size_t)(bn + lr) * K + kb;
#pragma unroll
        for (int j = 0; j < HC; j++) {
            int ch = lc0 + j;
            CP_ASYNC16(rowd + ch * 16, pa + ch * 8);
            CP_ASYNC16(rowd + TILE + ch * 16, pb + ch * 8);
        }
    };

    const int niter = (K / NSPLIT) / KT;

#pragma unroll
    for (int s = 0; s < STAGES - 1; s++) {
        if (s < niter) load_stage(s, kbase + s * KT);
        CP_COMMIT();
    }

    for (int it = 0; it < niter; it++) {
        cp_wait<STAGES - 2>();
        __syncthreads();

        const int buf = it % STAGES;
        const uint32_t aH = smb + buf * STG;
        const uint32_t bH = aH + TILE;

#pragma unroll
        for (int ks = 0; ks < 4; ks++) {
            const uint32_t aco = (uint32_t)(2 * ks + ca) * 16;
            const uint32_t bco = (uint32_t)(2 * ks + cbx) * 16;

            uint32_t ah[4][4];
#pragma unroll
            for (int mf = 0; mf < 4; mf++) {
                uint32_t ro = (uint32_t)(warp_m * 64 + mf * 16 + ra) * PITCH;
                ldsm4(ah[mf], aH + ro + aco);
            }
#pragma unroll
            for (int nb = 0; nb < 2; nb++) {
                uint32_t ro = (uint32_t)(warp_n * 32 + nb * 16 + rbx) * PITCH;
                uint32_t bh[4];
                ldsm4(bh, bH + ro + bco);
#pragma unroll
                for (int p = 0; p < 2; p++) {
                    const int nf = nb * 2 + p;
#pragma unroll
                    for (int mf = 0; mf < 4; mf++)
                        mma_f16(acc[mf][nf], ah[mf], bh[2 * p], bh[2 * p + 1]);
                }
            }
        }

        const int nidx = it + STAGES - 1;
        if (nidx < niter) load_stage(nidx % STAGES, kbase + nidx * KT);
        CP_COMMIT();
    }

    const int tr = lane >> 2;
    const int tc = lane & 3;
#pragma unroll
    for (int mf = 0; mf < 4; mf++) {
#pragma unroll
        for (int nf = 0; nf < 4; nf++) {
            int r0 = bm + warp_m * 64 + mf * 16 + tr;
            int col = bn + warp_n * 32 + nf * 8 + 2 * tc;
            *(float2*)(C + (size_t)r0 * N + col) = make_float2(acc[mf][nf][0], acc[mf][nf][1]);
            *(float2*)(C + (size_t)(r0 + 8) * N + col) =
                make_float2(acc[mf][nf][2], acc[mf][nf][3]);
        }
    }
}

// ---------------------------------------------------------------------------
// Split-K reduction: sum NSPLIT partials -> fp32 out (+ optional hi/lo split)
// ---------------------------------------------------------------------------
template <int NSPLIT, int DO_SPLIT>
__global__ void reduce_split_kernel(const float* __restrict__ part, float* __restrict__ out,
                                    __half* __restrict__ h, __half* __restrict__ l, int n4) {
    int i = blockIdx.x * blockDim.x + threadIdx.x;
    if (i >= n4) return;
    size_t stride4 = (size_t)n4;
    float4 v = ((const float4*)part)[i];
#pragma unroll
    for (int z = 1; z < NSPLIT; z++) {
        float4 w = ((const float4*)part)[z * stride4 + i];
        v.x += w.x; v.y += w.y; v.z += w.z; v.w += w.w;
    }
    ((float4*)out)[i] = v;
    if (DO_SPLIT) {
        float hx = __half2float(__float2half_rn(v.x));
        float hy = __half2float(__float2half_rn(v.y));
        float hz = __half2float(__float2half_rn(v.z));
        float hw = __half2float(__float2half_rn(v.w));
        ((__half2*)h)[i * 2] = __floats2half2_rn(hx, hy);
        ((__half2*)h)[i * 2 + 1] = __floats2half2_rn(hz, hw);
        ((__half2*)l)[i * 2] = __floats2half2_rn(v.x - hx, v.y - hy);
        ((__half2*)l)[i * 2 + 1] = __floats2half2_rn(v.z - hz, v.w - hw);
    }
}

// ---------------------------------------------------------------------------
// One-shot input split: fs, ft, w1, w2 -> (hi, lo) fp16, single launch
// ---------------------------------------------------------------------------
#define N4_FS (NROW * NFEAT / 4)
#define N4_W1 (NHID * NFEAT / 4)
#define N4_W2 (NCLASS * NHID / 4)

__global__ void split_all_kernel(const float* __restrict__ fs, const float* __restrict__ ft,
                                 const float* __restrict__ w1, const float* __restrict__ w2,
                                 __half* __restrict__ fsh, __half* __restrict__ fsl,
                                 __half* __restrict__ fth, __half* __restrict__ ftl,
                                 __half* __restrict__ w1h, __half* __restrict__ w1l,
                                 __half* __restrict__ w2h, __half* __restrict__ w2l) {
    int gi = blockIdx.x * blockDim.x + threadIdx.x;
    const float* src;
    __half *h, *l;
    int i;
    if (gi < N4_FS) {
        src = fs; h = fsh; l = fsl; i = gi;
    } else if (gi < 2 * N4_FS) {
        src = ft; h = fth; l = ftl; i = gi - N4_FS;
    } else if (gi < 2 * N4_FS + N4_W1) {
        src = w1; h = w1h; l = w1l; i = gi - 2 * N4_FS;
    } else if (gi < 2 * N4_FS + N4_W1 + N4_W2) {
        src = w2; h = w2h; l = w2l; i = gi - 2 * N4_FS - N4_W1;
    } else {
        return;
    }
    float4 v = ((const float4*)src)[i];
    float hx = __half2float(__float2half_rn(v.x));
    float hy = __half2float(__float2half_rn(v.y));
    float hz = __half2float(__float2half_rn(v.z));
    float hw = __half2float(__float2half_rn(v.w));
    ((__half2*)h)[i * 2] = __floats2half2_rn(hx, hy);
    ((__half2*)h)[i * 2 + 1] = __floats2half2_rn(hz, hw);
    ((__half2*)l)[i * 2] = __floats2half2_rn(v.x - hx, v.y - hy);
    ((__half2*)l)[i * 2 + 1] = __floats2half2_rn(v.z - hz, v.w - hw);
}

// ---------------------------------------------------------------------------
// Row softmax, register-resident: 8192 floats/row, 512 threads -> 4 float4
// per thread held in registers. No row smem buffer.
// ---------------------------------------------------------------------------
__global__ void __launch_bounds__(512, 2)
softmax_rows_kernel(const float* __restrict__ adj, __half* __restrict__ out, int N) {
    __shared__ float warp_red[16];
    __shared__ float bcast;

    const int tid = threadIdx.x;
    const int lane = tid & 31;
    const int wid = tid >> 5;
    const float* r = adj + (size_t)blockIdx.x * N;
    __half* o = out + (size_t)blockIdx.x * N;

    float4 v[4];
#pragma unroll
    for (int j = 0; j < 4; j++) v[j] = ((const float4*)r)[tid + j * 512];

    float mx = -INFINITY;
#pragma unroll
    for (int j = 0; j < 4; j++)
        mx = fmaxf(mx, fmaxf(fmaxf(v[j].x, v[j].y), fmaxf(v[j].z, v[j].w)));
#pragma unroll
    for (int off = 16; off > 0; off >>= 1) mx = fmaxf(mx, __shfl_xor_sync(0xffffffffu, mx, off));
    if (lane == 0) warp_red[wid] = mx;
    __syncthreads();
    if (tid == 0) {
        float m = warp_red[0];
#pragma unroll
        for (int w = 1; w < 16; w++) m = fmaxf(m, warp_red[w]);
        bcast = m;
    }
    __syncthreads();
    mx = bcast;
    __syncthreads();

    float sum = 0.0f;
#pragma unroll
    for (int j = 0; j < 4; j++) {
        v[j].x = __expf(v[j].x - mx); v[j].y = __expf(v[j].y - mx);
        v[j].z = __expf(v[j].z - mx); v[j].w = __expf(v[j].w - mx);
        sum += v[j].x + v[j].y + v[j].z + v[j].w;
    }
#pragma unroll
    for (int off = 16; off > 0; off >>= 1) sum += __shfl_xor_sync(0xffffffffu, sum, off);
    if (lane == 0) warp_red[wid] = sum;
    __syncthreads();
    if (tid == 0) {
        float s = 0.0f;
#pragma unroll
        for (int w = 0; w < 16; w++) s += warp_red[w];
        bcast = 1.0f / s;
    }
    __syncthreads();
    const float inv = bcast;

#pragma unroll
    for (int j = 0; j < 4; j++) {
        int idx = tid + j * 512;
        ((__half2*)o)[idx * 2] = __floats2half2_rn(v[j].x * inv, v[j].y * inv);
        ((__half2*)o)[idx * 2 + 1] = __floats2half2_rn(v[j].z * inv, v[j].w * inv);
    }
}

// ---------------------------------------------------------------------------
extern "C" void kernel_launch(void* const* d_in, const int* in_sizes, int n_in,
                              void* d_out, int out_size) {
    const float* fs = (const float*)d_in[0];
    const float* ft = (const float*)d_in[1];
    const float* w1 = (const float*)d_in[2];
    const float* w2 = (const float*)d_in[3];

    float* x1 = (float*)d_out;
    float* x2 = (float*)d_out + (size_t)NROW * NHID;

    float *adj, *p1, *p2;
    __half *adjh, *fsh, *fsl, *fth, *ftl, *w1h, *w1l, *w2h, *w2l;
    __half *Y1T, *Y2T, *x1h, *x1l;
    cudaGetSymbolAddress((void**)&adj, g_adj);
    cudaGetSymbolAddress((void**)&adjh, g_adjh);
    cudaGetSymbolAddress((void**)&fsh, g_fsh);
    cudaGetSymbolAddress((void**)&fsl, g_fsl);
    cudaGetSymbolAddress((void**)&fth, g_fth);
    cudaGetSymbolAddress((void**)&ftl, g_ftl);
    cudaGetSymbolAddress((void**)&w1h, g_w1h);
    cudaGetSymbolAddress((void**)&w1l, g_w1l);
    cudaGetSymbolAddress((void**)&w2h, g_w2h);
    cudaGetSymbolAddress((void**)&w2l, g_w2l);
    cudaGetSymbolAddress((void**)&Y1T, g_Y1T);
    cudaGetSymbolAddress((void**)&Y2T, g_Y2T);
    cudaGetSymbolAddress((void**)&x1h, g_x1h);
    cudaGetSymbolAddress((void**)&x1l, g_x1l);
    cudaGetSymbolAddress((void**)&p1, g_p1);
    cudaGetSymbolAddress((void**)&p2, g_p2);

    constexpr int SMEM_BIG = 3 * 61440;                     // hgemm3_256 (3-stage KT=32)
    constexpr int SMEM_SPLIT = 4 * (2 * 2 * 128 * 80);      // narrow 3-term (4-stage)
    constexpr int SMEM_SKW = 3 * (128 * 144 + 256 * 144);   // wide split-K
    constexpr int SMEM_SK = 3 * (2 * 128 * 144);            // narrow split-K
    cudaFuncSetAttribute(hgemm3_256_kernel,
                         cudaFuncAttributeMaxDynamicSharedMemorySize, SMEM_BIG);
    cudaFuncSetAttribute(hgemm_kernel<3, 32, 4, 2>,
                         cudaFuncAttributeMaxDynamicSharedMemorySize, SMEM_SPLIT);
    cudaFuncSetAttribute(hgemm1_splitk_wide_kernel,
                         cudaFuncAttributeMaxDynamicSharedMemorySize, SMEM_SKW);
    cudaFuncSetAttribute(hgemm1_splitk_kernel<KSPLIT2>,
                         cudaFuncAttributeMaxDynamicSharedMemorySize, SMEM_SK);

    // Side stream + fork/join events (created per call, intentionally leaked:
    // kernel_launch runs only for the correctness pass and the capture pass).
    cudaStream_t s2;
    cudaEvent_t evG, evJoin;
    cudaStreamCreateWithFlags(&s2, cudaStreamNonBlocking);
    cudaEventCreateWithFlags(&evG, cudaEventDisableTiming);
    cudaEventCreateWithFlags(&evJoin, cudaEventDisableTiming);

    // ---- pre-pass: all input splits in one launch
    {
        int total = 2 * N4_FS + N4_W1 + N4_W2;
        split_all_kernel<<<(total + 255) / 256, 256>>>(
            fs, ft, w1, w2, fsh, fsl, fth, ftl, w1h, w1l, w2h, w2l);
    }

    // 1) S = fs @ ft^T  (3-term, 256x128x32 tiles, 3-stage, 512 threads)
    hgemm3_256_kernel<<<dim3(NROW / 128, NROW / 256), 512, SMEM_BIG>>>(
        fsh, fsl, fth, ftl, adj, NROW, NROW, NFEAT);
    cudaEventRecord(evG, 0);

    // ---- fork AFTER GEMM1: Y1T (tensor-bound) overlaps softmax (DRAM-bound),
    //      instead of competing with GEMM1's tensor pipes.
    cudaStreamWaitEvent(s2, evG, 0);
    hgemm_kernel<3, 32, 4, 2><<<dim3(NROW / 128, NHID / 128), 256, SMEM_SPLIT, s2>>>(
        w1h, w1l, fsh, fsl, nullptr, Y1T, NHID, NROW, NFEAT);
    cudaEventRecord(evJoin, s2);

    // 2) softmax -> fp16 weights (register-resident), concurrent with Y1T
    softmax_rows_kernel<<<NROW, 512>>>(adj, adjh, NROW);

    // ---- join: x1 needs both adjh (main) and Y1T (side)
    cudaStreamWaitEvent(0, evJoin, 0);

    // 4) x1 = adjh @ Y1  (wide split-K; reduce + fused split)
    hgemm1_splitk_wide_kernel<<<dim3(NHID / 256, NROW / 128, KSPLIT), 512, SMEM_SKW>>>(
        adjh, Y1T, p1, NROW, NHID, NROW);
    {
        int n4 = NROW * NHID / 4;
        reduce_split_kernel<KSPLIT, 1><<<(n4 + 255) / 256, 256>>>(p1, x1, x1h, x1l, n4);
    }

    // 5) Y2T = w2 @ x1^T  [NCLASS, NROW]  (3-term, fp16 hi out)
    hgemm_kernel<3, 32, 4, 2><<<dim3(NROW / 128, NCLASS / 128), 256, SMEM_SPLIT>>>(
        w2h, w2l, x1h, x1l, nullptr, Y2T, NCLASS, NROW, NHID);

    // 6) x2 = adjh @ Y2  (split-K depth 4; reduce)
    hgemm1_splitk_kernel<KSPLIT2><<<dim3(NCLASS / 128, NROW / 128, KSPLIT2), 256, SMEM_SK>>>(
        adjh, Y2T, p2, NROW, NCLASS, NROW);
    {
        int n4 = NROW * NCLASS / 4;
        reduce_split_kernel<KSPLIT2, 0><<<(n4 + 255) / 256, 256>>>(p2, x2, nullptr, nullptr, n4);
    }
}